// round 11
// baseline (speedup 1.0000x reference)
#include <cuda_runtime.h>
#include <math.h>

#define BATCH 128
#define LQv   128
#define LAv   512
#define EMBD  300
#define FILT  400
#define EPAD  320
#define KCONV (3 * EPAD)   // 960

// ---- scratch (static __device__: no allocations allowed) ----
__device__ float    g_Q[BATCH * LQv * FILT];
__device__ float    g_A[BATCH * LAv * FILT];
__device__ float    g_T[BATCH * LQv * FILT];
__device__ unsigned g_Bw[KCONV * FILT];   // packed: [ntile=5][k'=960][80] tf32 bits
__device__ unsigned g_mq[BATCH * LQv];
__device__ unsigned g_ma[BATCH * LAv];
__device__ float    g_dxy[BATCH * 4];

__device__ __forceinline__ unsigned enc_f(float f) {
    int i = __float_as_int(f);
    return (unsigned)(i ^ ((i >> 31) | 0x80000000));
}
__device__ __forceinline__ float dec_f(unsigned u) {
    int i = (u & 0x80000000u) ? (int)(u ^ 0x80000000u) : ~(int)u;
    return __int_as_float(i);
}
__device__ __forceinline__ unsigned f2tf(float f) {
    unsigned u;
    asm("cvt.rna.tf32.f32 %0, %1;" : "=r"(u) : "f"(f));
    return u;
}
__device__ __forceinline__ void mma8(float* c, const unsigned* a, const unsigned* b) {
    asm("mma.sync.aligned.m16n8k8.row.col.f32.tf32.tf32.f32 "
        "{%0,%1,%2,%3},{%4,%5,%6,%7},{%8,%9},{%0,%1,%2,%3};"
        : "+f"(c[0]), "+f"(c[1]), "+f"(c[2]), "+f"(c[3])
        : "r"(a[0]), "r"(a[1]), "r"(a[2]), "r"(a[3]), "r"(b[0]), "r"(b[1]));
}
__device__ __forceinline__ void cp16(void* sptr, const void* gptr, int bytes) {
    unsigned s = (unsigned)__cvta_generic_to_shared(sptr);
    asm volatile("cp.async.cg.shared.global [%0], [%1], 16, %2;"
                 :: "r"(s), "l"(gptr), "r"(bytes));
}
__device__ __forceinline__ void cp16g(void* sptr, const void* gptr) {
    unsigned s = (unsigned)__cvta_generic_to_shared(sptr);
    asm volatile("cp.async.cg.shared.global [%0], [%1], 16;"
                 :: "r"(s), "l"(gptr));
}
#define CP_COMMIT() asm volatile("cp.async.commit_group;")
#define CP_WAIT0()  asm volatile("cp.async.wait_group 0;")
#define CP_WAIT1()  asm volatile("cp.async.wait_group 1;")

// ---- mbarrier + bulk helpers ----
__device__ __forceinline__ void mbar_init(unsigned addr, unsigned count) {
    asm volatile("mbarrier.init.shared.b64 [%0], %1;" :: "r"(addr), "r"(count) : "memory");
}
__device__ __forceinline__ void mbar_expect_tx(unsigned addr, unsigned bytes) {
    asm volatile("mbarrier.arrive.expect_tx.shared.b64 _, [%0], %1;"
                 :: "r"(addr), "r"(bytes) : "memory");
}
__device__ __forceinline__ void mbar_wait(unsigned addr, unsigned phase) {
    unsigned done = 0;
    while (!done) {
        asm volatile(
            "{\n\t.reg .pred p;\n\t"
            "mbarrier.try_wait.parity.shared.b64 p, [%1], %2;\n\t"
            "selp.b32 %0, 1, 0, p;\n\t}"
            : "=r"(done) : "r"(addr), "r"(phase) : "memory");
    }
}
__device__ __forceinline__ void cp_bulk(void* sptr, const void* gptr,
                                        unsigned bytes, unsigned mbar) {
    unsigned s = (unsigned)__cvta_generic_to_shared(sptr);
    asm volatile(
        "cp.async.bulk.shared::cta.global.mbarrier::complete_tx::bytes "
        "[%0], [%1], %2, [%3];"
        :: "r"(s), "l"(gptr), "r"(bytes), "r"(mbar) : "memory");
}
__device__ __forceinline__ unsigned smem_u32(const void* p) {
    unsigned r;
    asm("{ .reg .u64 t; cvta.to.shared.u64 t, %1; cvt.u32.u64 %0, t; }"
        : "=r"(r) : "l"(p));
    return r;
}

// ---------------------------------------------------------------------------
// 0) init
// ---------------------------------------------------------------------------
__global__ void init_max_kernel() {
    int idx = blockIdx.x * blockDim.x + threadIdx.x;
    unsigned v = enc_f(-2.0f);
    if (idx < BATCH * LQv) g_mq[idx] = v;
    if (idx < BATCH * LAv) g_ma[idx] = v;
    if (idx < BATCH * 4)   g_dxy[idx] = 0.0f;
}

// pack conv weights: g_Bw[nt][kp][nn] = tf32(cw[nt*80+nn][e][koff]), kp = koff*EPAD+e
__global__ void transpose_w_kernel(const float* __restrict__ cw) {
    int idx = blockIdx.x * blockDim.x + threadIdx.x;
    if (idx >= 5 * KCONV * 80) return;
    int nt = idx / (KCONV * 80);
    int r  = idx - nt * (KCONV * 80);
    int kp = r / 80, nn = r - kp * 80;
    int n = nt * 80 + nn;
    int koff = kp / EPAD, e = kp - koff * EPAD;
    float v = (e < EMBD) ? cw[(size_t)n * (EMBD * 3) + e * 3 + koff] : 0.0f;
    g_Bw[idx] = f2tf(v);
}

// ---------------------------------------------------------------------------
// 1) conv encode: 128 thr, 4 warps (2m x 2n), warp 64x40, block 128 tok x 80 f.
//    Flattened 30-step pipeline: s = (e-chunk, koff). B single-koff double
//    buffer via cp.async.bulk (1 bulk/step); E double buffer via cp.async,
//    advanced every 3rd step. smem 58.5 KB -> 3 CTAs/SM.
// ---------------------------------------------------------------------------
#define C_KC 32
#define C_NCH (EPAD / C_KC)       // 10
#define C_STEPS (3 * C_NCH)       // 30
#define E_PITCH 36
#define E_BUF  (130 * E_PITCH)    // 4680
#define B_PITCH 80
#define B_STG  (C_KC * B_PITCH)   // 2560 words per stage
#define B_BYTES (B_STG * 4)       // 10240
#define SM_MBAR 136               // two u64 mbarriers (words 136..139)
#define SM_E_OFF 144
#define SM_B_OFF (SM_E_OFF + 2 * E_BUF)          // 9504
#define SMEM_CONV ((SM_B_OFF + 2 * B_STG) * 4)   // 58496 B

__global__ __launch_bounds__(128, 3) void conv_encode_kernel(
    const int* __restrict__ qtok, const int* __restrict__ atok,
    const float* __restrict__ emb, const float* __restrict__ cb, int is_q)
{
    extern __shared__ unsigned sm[];
    int*      s_tok = (int*)sm;
    unsigned* E     = sm + SM_E_OFF;
    unsigned* Bsm   = sm + SM_B_OFF;

    const int b   = blockIdx.z;
    const int nt  = blockIdx.y;
    const int n0  = nt * 80;
    const int tid = threadIdx.x;
    const int wid = tid >> 5, lane = tid & 31;
    const int g   = lane >> 2, tig = lane & 3;
    const int wm  = wid & 1,  wn  = wid >> 1;
    const int mwb = wm * 64,  nwb = wn * 40;

    const unsigned smem_base = smem_u32(sm);
    const unsigned mbarB0 = smem_base + SM_MBAR * 4;
    const unsigned mbarB1 = smem_base + (SM_MBAR + 2) * 4;

    const int* tok = is_q ? qtok : atok;
    float* dst     = is_q ? g_Q : g_A;
    const int L    = is_q ? LQv : LAv;
    const int t0   = blockIdx.x * 128;

    if (tid == 0) { mbar_init(mbarB0, 1); mbar_init(mbarB1, 1); }
    for (int r = tid; r < 130; r += 128) {
        int tg = t0 + r - 1;
        s_tok[r] = (tg >= 0 && tg < L) ? tok[b * L + tg] : 0;
    }
    __syncthreads();

    // E prefetch (cp.async, zfill tail), one e-chunk into buffer ec&1
    auto prefetch_E = [&](int ec) {
        int e0 = ec * C_KC;
        unsigned* Eb = E + (ec & 1) * E_BUF;
        for (int i = tid; i < 130 * 8; i += 128) {
            int r = i >> 3, sg = i & 7;
            int e = e0 + sg * 4;
            int el = 300 - e; el = el < 0 ? 0 : (el > 4 ? 4 : el);
            int bytes = el * 4;
            const float* src = emb + (bytes ? ((size_t)s_tok[r] * EMBD + e) : 0);
            cp16(&Eb[r * E_PITCH + sg * 4], src, bytes);
        }
        CP_COMMIT();
    };
    // B prefetch (single bulk) for step s into buffer s&1
    auto prefetch_B = [&](int s) {
        if (tid == 0) {
            int ec = s / 3, ko = s - ec * 3;
            unsigned mb = (s & 1) ? mbarB1 : mbarB0;
            mbar_expect_tx(mb, B_BYTES);
            const unsigned* src =
                g_Bw + ((size_t)nt * KCONV + ko * EPAD + ec * C_KC) * 80;
            cp_bulk(Bsm + (s & 1) * B_STG, src, B_BYTES, mb);
        }
    };

    float c[4][5][4];
#pragma unroll
    for (int i = 0; i < 4; i++)
#pragma unroll
        for (int j = 0; j < 5; j++)
#pragma unroll
            for (int k = 0; k < 4; k++) c[i][j][k] = 0.0f;

    prefetch_E(0);
    prefetch_B(0);

    for (int s = 0; s < C_STEPS; s++) {
        const int ec = s / 3, ko = s - ec * 3;
        const int ebs = ec & 1, bbs = s & 1;

        // wait: B of step s; E of chunk ec (already waited unless new chunk)
        mbar_wait(bbs ? mbarB1 : mbarB0, (s >> 1) & 1);
        if (ko == 0) CP_WAIT0();
        __syncthreads();   // all buffers ready AND previous step fully consumed

        // prefetches for the future (safe: targets were released above)
        if (ko == 0 && ec + 1 < C_NCH) prefetch_E(ec + 1);
        if (s + 1 < C_STEPS) prefetch_B(s + 1);

        const unsigned* Eb = E + ebs * E_BUF;
        const unsigned* Bk = Bsm + bbs * B_STG;

#pragma unroll
        for (int kb = 0; kb < C_KC / 8; kb++) {
            int kk = kb * 8;
            unsigned a[4][4];
#pragma unroll
            for (int ms = 0; ms < 4; ms++) {
                int row = mwb + ms * 16 + g + ko;
                a[ms][0] = Eb[(row)     * E_PITCH + kk + tig];
                a[ms][1] = Eb[(row + 8) * E_PITCH + kk + tig];
                a[ms][2] = Eb[(row)     * E_PITCH + kk + tig + 4];
                a[ms][3] = Eb[(row + 8) * E_PITCH + kk + tig + 4];
            }
#pragma unroll
            for (int ns = 0; ns < 5; ns++) {
                unsigned bf[2];
                int nb = nwb + ns * 8 + g;
                bf[0] = Bk[(kk + tig)     * B_PITCH + nb];
                bf[1] = Bk[(kk + tig + 4) * B_PITCH + nb];
#pragma unroll
                for (int ms = 0; ms < 4; ms++)
                    mma8(c[ms][ns], a[ms], bf);
            }
        }
    }

#pragma unroll
    for (int ms = 0; ms < 4; ms++) {
#pragma unroll
        for (int ns = 0; ns < 5; ns++) {
            int col = n0 + nwb + ns * 8 + 2 * tig;
            float2 bias = *(const float2*)&cb[col];
            int row0 = t0 + mwb + ms * 16 + g;
            *(float2*)&dst[((size_t)b * L + row0) * FILT + col] =
                make_float2(c[ms][ns][0] + bias.x, c[ms][ns][1] + bias.y);
            *(float2*)&dst[((size_t)b * L + row0 + 8) * FILT + col] =
                make_float2(c[ms][ns][2] + bias.x, c[ms][ns][3] + bias.y);
        }
    }
}

// ---------------------------------------------------------------------------
// 2) T = Qm @ W : 128 thr, warp 64x40, 2-stage cp.async (hidden under convA)
// ---------------------------------------------------------------------------
#define T_KC 40
#define T_AP 44
#define T_BP 88
#define T_ABUF (128 * T_AP)
#define T_BOFF (2 * T_ABUF)
#define T_BBUF (T_KC * T_BP)
#define SMEM_T ((T_BOFF + 2 * T_BBUF) * 4)

__global__ __launch_bounds__(128, 2) void gemm_T_kernel(const float* __restrict__ W)
{
    extern __shared__ unsigned sm[];
    unsigned* Asm = sm;
    unsigned* Bsm = sm + T_BOFF;

    const int b  = blockIdx.z;
    const int n0 = blockIdx.x * 80;
    const int tid  = threadIdx.x;
    const int wid  = tid >> 5, lane = tid & 31;
    const int g    = lane >> 2, tig = lane & 3;
    const int wm   = wid & 1,  wn  = wid >> 1;
    const int mwb  = wm * 64, nwb = wn * 40;

    const float* Qb = g_Q + (size_t)b * LQv * FILT;

    auto prefetch = [&](int ch, int bs) {
        int k0 = ch * T_KC;
        unsigned* Ab = Asm + bs * T_ABUF;
        unsigned* Bb = Bsm + bs * T_BBUF;
#pragma unroll
        for (int it = 0; it < 10; it++) {
            int i = tid + it * 128;
            int m = i / 10, k4 = i - m * 10;
            cp16g(&Ab[m * T_AP + k4 * 4], Qb + (size_t)m * FILT + k0 + k4 * 4);
        }
        for (int i = tid; i < T_KC * 20; i += 128) {
            int kc = i / 20, sg = i - kc * 20;
            cp16g(&Bb[kc * T_BP + sg * 4], W + (size_t)(k0 + kc) * FILT + n0 + sg * 4);
        }
    };

    float c[4][5][4];
#pragma unroll
    for (int i = 0; i < 4; i++)
#pragma unroll
        for (int j = 0; j < 5; j++)
#pragma unroll
            for (int k = 0; k < 4; k++) c[i][j][k] = 0.0f;

    prefetch(0, 0);
    CP_COMMIT();

    for (int ch = 0; ch < FILT / T_KC; ch++) {
        int bs = ch & 1;
        if (ch + 1 < FILT / T_KC) prefetch(ch + 1, bs ^ 1);
        CP_COMMIT();
        CP_WAIT1();
        __syncthreads();

        const unsigned* Ab = Asm + bs * T_ABUF;
        const unsigned* Bb = Bsm + bs * T_BBUF;

#pragma unroll
        for (int kb = 0; kb < T_KC / 8; kb++) {
            int kk = kb * 8;
            unsigned a[4][4];
#pragma unroll
            for (int ms = 0; ms < 4; ms++) {
                int row = mwb + ms * 16 + g;
                a[ms][0] = Ab[(row)     * T_AP + kk + tig];
                a[ms][1] = Ab[(row + 8) * T_AP + kk + tig];
                a[ms][2] = Ab[(row)     * T_AP + kk + tig + 4];
                a[ms][3] = Ab[(row + 8) * T_AP + kk + tig + 4];
            }
#pragma unroll
            for (int ns = 0; ns < 5; ns++) {
                unsigned bf[2];
                int nb = nwb + ns * 8 + g;
                bf[0] = Bb[(kk + tig)     * T_BP + nb];
                bf[1] = Bb[(kk + tig + 4) * T_BP + nb];
#pragma unroll
                for (int ms = 0; ms < 4; ms++)
                    mma8(c[ms][ns], a[ms], bf);
            }
        }
        __syncthreads();
    }

#pragma unroll
    for (int ms = 0; ms < 4; ms++) {
#pragma unroll
        for (int ns = 0; ns < 5; ns++) {
            int col = n0 + nwb + ns * 8 + 2 * tig;
            int row0 = mwb + ms * 16 + g;
            *(float2*)&g_T[((size_t)b * LQv + row0) * FILT + col] =
                make_float2(c[ms][ns][0], c[ms][ns][1]);
            *(float2*)&g_T[((size_t)b * LQv + row0 + 8) * FILT + col] =
                make_float2(c[ms][ns][2], c[ms][ns][3]);
        }
    }
}

// ---------------------------------------------------------------------------
// 3) G = tanh(T @ A^T) fused maxes: 256 thr, 8 warps (2m x 4n), warp 64x32,
//    block 128 x 128, 2-stage cp.async.bulk + mbarrier (1 bulk per thread/chunk)
// ---------------------------------------------------------------------------
#define G_KC 40
#define G_AP 44
#define G_ABUF (128 * G_AP)
#define G_BOFF (2 * G_ABUF)
#define G_BBUF (128 * G_AP)
#define G_RED  (G_BOFF + 2 * G_BBUF)
#define G_MBAR (G_RED + 256)
#define SMEM_G ((G_MBAR + 8) * 4)
#define G_ROW_BYTES (G_KC * 4)    // 160

__global__ __launch_bounds__(256, 2) void gemm_G_kernel()
{
    extern __shared__ unsigned sm[];
    unsigned* Asm  = sm;
    unsigned* Bsm  = sm + G_BOFF;
    unsigned* srow = sm + G_RED;
    unsigned* scol = sm + G_RED + 128;

    const int b  = blockIdx.y;
    const int a0 = blockIdx.x * 128;
    const int tid  = threadIdx.x;
    const int wid  = tid >> 5, lane = tid & 31;
    const int g    = lane >> 2, tig = lane & 3;
    const int wm   = wid & 1,  wn  = wid >> 1;
    const int mwb  = wm * 64, nwb = wn * 32;

    const unsigned smem_base = smem_u32(sm);
    const unsigned mbar0 = smem_base + G_MBAR * 4;
    const unsigned mbar1 = smem_base + (G_MBAR + 2) * 4;

    if (tid == 0) { mbar_init(mbar0, 1); mbar_init(mbar1, 1); }
    if (tid < 128) { srow[tid] = enc_f(-2.0f); scol[tid] = enc_f(-2.0f); }
    __syncthreads();

    const float* Tb  = g_T + (size_t)b * LQv * FILT;
    const float* Ab0 = g_A + ((size_t)b * LAv + a0) * FILT;

    auto prefetch = [&](int ch, int bs) {
        int k0 = ch * G_KC;
        unsigned mb = bs ? mbar1 : mbar0;
        if (tid == 0) mbar_expect_tx(mb, 256 * G_ROW_BYTES);
        if (tid < 128) {
            cp_bulk(&(Asm + bs * G_ABUF)[tid * G_AP],
                    Tb + (size_t)tid * FILT + k0, G_ROW_BYTES, mb);
        } else {
            int n = tid - 128;
            cp_bulk(&(Bsm + bs * G_BBUF)[n * G_AP],
                    Ab0 + (size_t)n * FILT + k0, G_ROW_BYTES, mb);
        }
    };

    float c[4][4][4];
#pragma unroll
    for (int i = 0; i < 4; i++)
#pragma unroll
        for (int j = 0; j < 4; j++)
#pragma unroll
            for (int k = 0; k < 4; k++) c[i][j][k] = 0.0f;

    prefetch(0, 0);

    for (int ch = 0; ch < FILT / G_KC; ch++) {
        int bs = ch & 1;
        if (ch + 1 < FILT / G_KC) prefetch(ch + 1, bs ^ 1);
        mbar_wait(bs ? mbar1 : mbar0, (ch >> 1) & 1);
        __syncthreads();

        const unsigned* Abuf = Asm + bs * G_ABUF;
        const unsigned* Bbuf = Bsm + bs * G_BBUF;

#pragma unroll
        for (int kb = 0; kb < G_KC / 8; kb++) {
            int kk = kb * 8;
            unsigned a[4][4];
#pragma unroll
            for (int ms = 0; ms < 4; ms++) {
                int row = mwb + ms * 16 + g;
                a[ms][0] = Abuf[(row)     * G_AP + kk + tig];
                a[ms][1] = Abuf[(row + 8) * G_AP + kk + tig];
                a[ms][2] = Abuf[(row)     * G_AP + kk + tig + 4];
                a[ms][3] = Abuf[(row + 8) * G_AP + kk + tig + 4];
            }
#pragma unroll
            for (int ns = 0; ns < 4; ns++) {
                unsigned bf[2];
                int nb = nwb + ns * 8 + g;
                bf[0] = Bbuf[nb * G_AP + kk + tig];
                bf[1] = Bbuf[nb * G_AP + kk + tig + 4];
#pragma unroll
                for (int ms = 0; ms < 4; ms++)
                    mma8(c[ms][ns], a[ms], bf);
            }
        }
        __syncthreads();
    }

#pragma unroll
    for (int ms = 0; ms < 4; ms++) {
        float r0 = -2.0f, r1 = -2.0f;
#pragma unroll
        for (int ns = 0; ns < 4; ns++) {
#pragma unroll
            for (int k = 0; k < 4; k++) c[ms][ns][k] = tanhf(c[ms][ns][k]);
            r0 = fmaxf(r0, fmaxf(c[ms][ns][0], c[ms][ns][1]));
            r1 = fmaxf(r1, fmaxf(c[ms][ns][2], c[ms][ns][3]));
        }
        atomicMax(&srow[mwb + ms * 16 + g],     enc_f(r0));
        atomicMax(&srow[mwb + ms * 16 + g + 8], enc_f(r1));
    }
#pragma unroll
    for (int ns = 0; ns < 4; ns++) {
        float c0 = -2.0f, c1 = -2.0f;
#pragma unroll
        for (int ms = 0; ms < 4; ms++) {
            c0 = fmaxf(c0, fmaxf(c[ms][ns][0], c[ms][ns][2]));
            c1 = fmaxf(c1, fmaxf(c[ms][ns][1], c[ms][ns][3]));
        }
        int nb = nwb + ns * 8 + 2 * tig;
        atomicMax(&scol[nb],     enc_f(c0));
        atomicMax(&scol[nb + 1], enc_f(c1));
    }
    __syncthreads();

    if (tid < 128) {
        atomicMax(&g_mq[b * LQv + tid], srow[tid]);
        atomicMax(&g_ma[b * LAv + a0 + tid], scol[tid]);
    }
}

// ---------------------------------------------------------------------------
// 4a) per-batch softmax; writes normalized weights back into g_mq / g_ma
// ---------------------------------------------------------------------------
__device__ __forceinline__ float warp_max(float v) {
#pragma unroll
    for (int o = 16; o > 0; o >>= 1) v = fmaxf(v, __shfl_xor_sync(0xffffffffu, v, o));
    return v;
}
__device__ __forceinline__ float warp_sum(float v) {
#pragma unroll
    for (int o = 16; o > 0; o >>= 1) v += __shfl_xor_sync(0xffffffffu, v, o);
    return v;
}

__global__ __launch_bounds__(256) void softmax_kernel()
{
    __shared__ float sq[LQv], sa[LAv];
    __shared__ float smax[2], ssum[2];

    const int b = blockIdx.x;
    const int tid = threadIdx.x;
    const int lane = tid & 31;

    for (int q = tid; q < LQv; q += 256) sq[q] = dec_f(g_mq[b * LQv + q]);
    for (int a = tid; a < LAv; a += 256) sa[a] = dec_f(g_ma[b * LAv + a]);
    __syncthreads();

    if (tid < 32) {
        float m = -1e30f;
        for (int q = lane; q < LQv; q += 32) m = fmaxf(m, sq[q]);
        m = warp_max(m);
        if (lane == 0) smax[0] = m;
    } else if (tid < 64) {
        float m = -1e30f;
        for (int a = lane; a < LAv; a += 32) m = fmaxf(m, sa[a]);
        m = warp_max(m);
        if (lane == 0) smax[1] = m;
    }
    __syncthreads();
    for (int q = tid; q < LQv; q += 256) sq[q] = expf(sq[q] - smax[0]);
    for (int a = tid; a < LAv; a += 256) sa[a] = expf(sa[a] - smax[1]);
    __syncthreads();
    if (tid < 32) {
        float s = 0.0f;
        for (int q = lane; q < LQv; q += 32) s += sq[q];
        s = warp_sum(s);
        if (lane == 0) ssum[0] = s;
    } else if (tid < 64) {
        float s = 0.0f;
        for (int a = lane; a < LAv; a += 32) s += sa[a];
        s = warp_sum(s);
        if (lane == 0) ssum[1] = s;
    }
    __syncthreads();
    float invq = 1.0f / ssum[0], inva = 1.0f / ssum[1];
    for (int q = tid; q < LQv; q += 256)
        g_mq[b * LQv + q] = __float_as_uint(sq[q] * invq);
    for (int a = tid; a < LAv; a += 256)
        g_ma[b * LAv + a] = __float_as_uint(sa[a] * inva);
}

// ---------------------------------------------------------------------------
// 4b) pooling partials: grid (128 b, 2 halves), 256 thr, 200 f each
// ---------------------------------------------------------------------------
__global__ __launch_bounds__(256) void pool_kernel()
{
    __shared__ float wq[LQv], wa[LAv];
    __shared__ float rd[256], rx[256], ry[256];

    const int b = blockIdx.x;
    const int f0 = blockIdx.y * 200;
    const int tid = threadIdx.x;

    for (int q = tid; q < LQv; q += 256) wq[q] = __uint_as_float(g_mq[b * LQv + q]);
    for (int a = tid; a < LAv; a += 256) wa[a] = __uint_as_float(g_ma[b * LAv + a]);
    __syncthreads();

    float d = 0.0f, x = 0.0f, y = 0.0f;
    if (tid < 200) {
        int f = f0 + tid;
        const float* qp = g_Q + (size_t)b * LQv * FILT + f;
        float accq = 0.0f;
#pragma unroll 8
        for (int q = 0; q < LQv; q++) accq += qp[(size_t)q * FILT] * wq[q];
        const float* ap = g_A + (size_t)b * LAv * FILT + f;
        float acca = 0.0f;
#pragma unroll 8
        for (int a = 0; a < LAv; a++) acca += ap[(size_t)a * FILT] * wa[a];
        d = accq * acca; x = accq * accq; y = acca * acca;
    }
    rd[tid] = d; rx[tid] = x; ry[tid] = y;
    __syncthreads();
#pragma unroll
    for (int s = 128; s > 0; s >>= 1) {
        if (tid < s) {
            rd[tid] += rd[tid + s];
            rx[tid] += rx[tid + s];
            ry[tid] += ry[tid + s];
        }
        __syncthreads();
    }
    if (tid == 0) {
        atomicAdd(&g_dxy[b * 4 + 0], rd[0]);
        atomicAdd(&g_dxy[b * 4 + 1], rx[0]);
        atomicAdd(&g_dxy[b * 4 + 2], ry[0]);
    }
}

// ---------------------------------------------------------------------------
// 4c) final cosine
// ---------------------------------------------------------------------------
__global__ __launch_bounds__(128) void final_out_kernel(float* __restrict__ out)
{
    int b = threadIdx.x;
    float D = g_dxy[b * 4 + 0];
    float X = g_dxy[b * 4 + 1];
    float Y = g_dxy[b * 4 + 2];
    float nq = fmaxf(sqrtf(X), 1e-8f);
    float na = fmaxf(sqrtf(Y), 1e-8f);
    out[b] = D / (nq * na);
}

// ---------------------------------------------------------------------------
// launch — two streams: convA on s2 overlaps convQ + gemm_T on main
// ---------------------------------------------------------------------------
extern "C" void kernel_launch(void* const* d_in, const int* in_sizes, int n_in,
                              void* d_out, int out_size)
{
    const int*   questions = (const int*)d_in[0];
    const int*   answers   = (const int*)d_in[1];
    const float* emb       = (const float*)d_in[2];
    const float* conv_w    = (const float*)d_in[3];
    const float* conv_b    = (const float*)d_in[4];
    const float* W         = (const float*)d_in[5];
    float*       out       = (float*)d_out;

    (void)in_sizes; (void)n_in; (void)out_size;

    static bool init_done = false;
    static cudaStream_t s2;
    static cudaEvent_t evFork, evJoin;
    if (!init_done) {
        cudaFuncSetAttribute(conv_encode_kernel,
                             cudaFuncAttributeMaxDynamicSharedMemorySize, SMEM_CONV);
        cudaFuncSetAttribute(gemm_T_kernel,
                             cudaFuncAttributeMaxDynamicSharedMemorySize, SMEM_T);
        cudaFuncSetAttribute(gemm_G_kernel,
                             cudaFuncAttributeMaxDynamicSharedMemorySize, SMEM_G);
        cudaStreamCreateWithFlags(&s2, cudaStreamNonBlocking);
        cudaEventCreateWithFlags(&evFork, cudaEventDisableTiming);
        cudaEventCreateWithFlags(&evJoin, cudaEventDisableTiming);
        init_done = true;
    }

    init_max_kernel<<<(BATCH * LAv + 255) / 256, 256>>>();
    transpose_w_kernel<<<(5 * KCONV * 80 + 255) / 256, 256>>>(conv_w);

    // fork: convA on s2 after transpose
    cudaEventRecord(evFork, 0);
    cudaStreamWaitEvent(s2, evFork, 0);

    conv_encode_kernel<<<dim3(4, 5, BATCH), 128, SMEM_CONV, s2>>>(
        questions, answers, emb, conv_b, 0);   // answers

    // main stream: convQ then T (Q-only dependency)
    conv_encode_kernel<<<dim3(1, 5, BATCH), 128, SMEM_CONV>>>(
        questions, answers, emb, conv_b, 1);   // questions
    gemm_T_kernel<<<dim3(FILT / 80, 1, BATCH), 128, SMEM_T>>>(W);

    // join: G needs A (s2) and T (main)
    cudaEventRecord(evJoin, s2);
    cudaStreamWaitEvent(0, evJoin, 0);

    gemm_G_kernel<<<dim3(LAv / 128, BATCH), 256, SMEM_G>>>();

    softmax_kernel<<<BATCH, 256>>>();
    pool_kernel<<<dim3(BATCH, 2), 256>>>();
    final_out_kernel<<<1, 128>>>(out);
}

// round 12
// speedup vs baseline: 1.2861x; 1.2861x over previous
#include <cuda_runtime.h>
#include <cuda_bf16.h>
#include <math.h>

#define BATCH 128
#define LQv   128
#define LAv   512
#define EMBD  300
#define FILT  400
#define EPAD  320
#define VROWS 50001
#define KP_TOT 480            // 3 koff * 160 kp

// ---- scratch (static __device__: no allocations allowed) ----
__device__ float    g_Q[BATCH * LQv * FILT];
__device__ float    g_A[BATCH * LAv * FILT];
__device__ float    g_T[BATCH * LQv * FILT];
__device__ unsigned g_Bw[5 * KP_TOT * 80];     // bf16-pair packed conv weights
__device__ unsigned g_Ebf[(size_t)VROWS * 160]; // bf16-pair padded emb table
__device__ unsigned g_mq[BATCH * LQv];
__device__ unsigned g_ma[BATCH * LAv];
__device__ float    g_dxy[BATCH * 4];

__device__ __forceinline__ unsigned enc_f(float f) {
    int i = __float_as_int(f);
    return (unsigned)(i ^ ((i >> 31) | 0x80000000));
}
__device__ __forceinline__ float dec_f(unsigned u) {
    int i = (u & 0x80000000u) ? (int)(u ^ 0x80000000u) : ~(int)u;
    return __int_as_float(i);
}
__device__ __forceinline__ unsigned f2tf(float f) {
    unsigned u;
    asm("cvt.rna.tf32.f32 %0, %1;" : "=r"(u) : "f"(f));
    return u;
}
__device__ __forceinline__ unsigned pack_bf2(float lo, float hi) {
    unsigned short l = __bfloat16_as_ushort(__float2bfloat16(lo));
    unsigned short h = __bfloat16_as_ushort(__float2bfloat16(hi));
    return (unsigned)l | ((unsigned)h << 16);
}
__device__ __forceinline__ void mma8(float* c, const unsigned* a, const unsigned* b) {
    asm("mma.sync.aligned.m16n8k8.row.col.f32.tf32.tf32.f32 "
        "{%0,%1,%2,%3},{%4,%5,%6,%7},{%8,%9},{%0,%1,%2,%3};"
        : "+f"(c[0]), "+f"(c[1]), "+f"(c[2]), "+f"(c[3])
        : "r"(a[0]), "r"(a[1]), "r"(a[2]), "r"(a[3]), "r"(b[0]), "r"(b[1]));
}
__device__ __forceinline__ void mma16(float* c, const unsigned* a, const unsigned* b) {
    asm("mma.sync.aligned.m16n8k16.row.col.f32.bf16.bf16.f32 "
        "{%0,%1,%2,%3},{%4,%5,%6,%7},{%8,%9},{%0,%1,%2,%3};"
        : "+f"(c[0]), "+f"(c[1]), "+f"(c[2]), "+f"(c[3])
        : "r"(a[0]), "r"(a[1]), "r"(a[2]), "r"(a[3]), "r"(b[0]), "r"(b[1]));
}
__device__ __forceinline__ void cp16g(void* sptr, const void* gptr) {
    unsigned s = (unsigned)__cvta_generic_to_shared(sptr);
    asm volatile("cp.async.cg.shared.global [%0], [%1], 16;"
                 :: "r"(s), "l"(gptr));
}
#define CP_COMMIT() asm volatile("cp.async.commit_group;")
#define CP_WAIT0()  asm volatile("cp.async.wait_group 0;")
#define CP_WAIT1()  asm volatile("cp.async.wait_group 1;")

// ---- mbarrier + bulk helpers ----
__device__ __forceinline__ void mbar_init(unsigned addr, unsigned count) {
    asm volatile("mbarrier.init.shared.b64 [%0], %1;" :: "r"(addr), "r"(count) : "memory");
}
__device__ __forceinline__ void mbar_expect_tx(unsigned addr, unsigned bytes) {
    asm volatile("mbarrier.arrive.expect_tx.shared.b64 _, [%0], %1;"
                 :: "r"(addr), "r"(bytes) : "memory");
}
__device__ __forceinline__ void mbar_wait(unsigned addr, unsigned phase) {
    unsigned done = 0;
    while (!done) {
        asm volatile(
            "{\n\t.reg .pred p;\n\t"
            "mbarrier.try_wait.parity.shared.b64 p, [%1], %2;\n\t"
            "selp.b32 %0, 1, 0, p;\n\t}"
            : "=r"(done) : "r"(addr), "r"(phase) : "memory");
    }
}
__device__ __forceinline__ void cp_bulk(void* sptr, const void* gptr,
                                        unsigned bytes, unsigned mbar) {
    unsigned s = (unsigned)__cvta_generic_to_shared(sptr);
    asm volatile(
        "cp.async.bulk.shared::cta.global.mbarrier::complete_tx::bytes "
        "[%0], [%1], %2, [%3];"
        :: "r"(s), "l"(gptr), "r"(bytes), "r"(mbar) : "memory");
}
__device__ __forceinline__ unsigned smem_u32(const void* p) {
    unsigned r;
    asm("{ .reg .u64 t; cvta.to.shared.u64 t, %1; cvt.u32.u64 %0, t; }"
        : "=r"(r) : "l"(p));
    return r;
}

// ---------------------------------------------------------------------------
// 0) init + weight pack + emb convert
// ---------------------------------------------------------------------------
__global__ void init_max_kernel() {
    int idx = blockIdx.x * blockDim.x + threadIdx.x;
    unsigned v = enc_f(-2.0f);
    if (idx < BATCH * LQv) g_mq[idx] = v;
    if (idx < BATCH * LAv) g_ma[idx] = v;
    if (idx < BATCH * 4)   g_dxy[idx] = 0.0f;
}

// g_Bw[nt][kp][nn]: kp = ko*160 + ep; word = (bf16 w[2ep], bf16 w[2ep+1]) for filter nt*80+nn
__global__ void transpose_w_kernel(const float* __restrict__ cw) {
    int idx = blockIdx.x * blockDim.x + threadIdx.x;
    if (idx >= 5 * KP_TOT * 80) return;
    int nt = idx / (KP_TOT * 80);
    int r  = idx - nt * (KP_TOT * 80);
    int kp = r / 80, nn = r - kp * 80;
    int n = nt * 80 + nn;
    int ko = kp / 160, ep = kp - ko * 160;
    int e0 = 2 * ep, e1 = 2 * ep + 1;
    float v0 = (e0 < EMBD) ? cw[(size_t)n * (EMBD * 3) + e0 * 3 + ko] : 0.0f;
    float v1 = (e1 < EMBD) ? cw[(size_t)n * (EMBD * 3) + e1 * 3 + ko] : 0.0f;
    g_Bw[idx] = pack_bf2(v0, v1);
}

// g_Ebf[row][wp]: word = (bf16 emb[row][2wp], bf16 emb[row][2wp+1]), zero-padded to 320
__global__ void emb_cvt_kernel(const float* __restrict__ emb) {
    size_t idx = (size_t)blockIdx.x * blockDim.x + threadIdx.x;
    if (idx >= (size_t)VROWS * 160) return;
    int row = (int)(idx / 160), wp = (int)(idx - (size_t)row * 160);
    int e0 = 2 * wp, e1 = e0 + 1;
    float v0 = (e0 < EMBD) ? emb[(size_t)row * EMBD + e0] : 0.0f;
    float v1 = (e1 < EMBD) ? emb[(size_t)row * EMBD + e1] : 0.0f;
    g_Ebf[idx] = pack_bf2(v0, v1);
}

// ---------------------------------------------------------------------------
// 1) conv encode (bf16 m16n8k16): 128 thr, 4 warps (2m x 2n), warp 64x40,
//    block 128 tok x 80 filt. Flattened 30-step pipeline (e-chunk, koff):
//    B single-koff double buffer via one 5KB bulk/step; E double buffer via
//    cp.async (64B/row), advanced every 3rd step. smem ~31.6 KB.
// ---------------------------------------------------------------------------
#define C_NCH  10                 // e-chunks of 32
#define C_STEPS 30
#define E_PITCH 20                // u32 words per row (16 data + 4 pad)
#define E_BUF  (130 * E_PITCH)    // 2600
#define B_PITCH 80
#define B_STG  (16 * B_PITCH)     // 1280 words
#define B_BYTES (B_STG * 4)       // 5120
#define SM_MBAR 136
#define SM_E_OFF 144
#define SM_B_OFF (SM_E_OFF + 2 * E_BUF)          // 5344
#define SMEM_CONV ((SM_B_OFF + 2 * B_STG) * 4)   // 31616 B

__global__ __launch_bounds__(128, 3) void conv_encode_kernel(
    const int* __restrict__ qtok, const int* __restrict__ atok,
    const float* __restrict__ cb, int is_q)
{
    extern __shared__ unsigned sm[];
    int*      s_tok = (int*)sm;
    unsigned* E     = sm + SM_E_OFF;
    unsigned* Bsm   = sm + SM_B_OFF;

    const int b   = blockIdx.z;
    const int nt  = blockIdx.y;
    const int n0  = nt * 80;
    const int tid = threadIdx.x;
    const int wid = tid >> 5, lane = tid & 31;
    const int g   = lane >> 2, tig = lane & 3;
    const int wm  = wid & 1,  wn  = wid >> 1;
    const int mwb = wm * 64,  nwb = wn * 40;

    const unsigned smem_base = smem_u32(sm);
    const unsigned mbarB0 = smem_base + SM_MBAR * 4;
    const unsigned mbarB1 = smem_base + (SM_MBAR + 2) * 4;

    const int* tok = is_q ? qtok : atok;
    float* dst     = is_q ? g_Q : g_A;
    const int L    = is_q ? LQv : LAv;
    const int t0   = blockIdx.x * 128;

    if (tid == 0) { mbar_init(mbarB0, 1); mbar_init(mbarB1, 1); }
    for (int r = tid; r < 130; r += 128) {
        int tg = t0 + r - 1;
        s_tok[r] = (tg >= 0 && tg < L) ? tok[b * L + tg] : 0;
    }
    __syncthreads();

    // E prefetch: chunk ec -> buffer ec&1; 16 words (64B) per row, 4 cp16 each
    auto prefetch_E = [&](int ec) {
        unsigned* Eb = E + (ec & 1) * E_BUF;
        int w0 = ec * 16;
        for (int i = tid; i < 130 * 4; i += 128) {
            int r = i >> 2, sg = i & 3;
            cp16g(&Eb[r * E_PITCH + sg * 4],
                  g_Ebf + (size_t)s_tok[r] * 160 + w0 + sg * 4);
        }
        CP_COMMIT();
    };
    // B prefetch (single bulk) for step s into buffer s&1
    auto prefetch_B = [&](int s) {
        if (tid == 0) {
            int ec = s / 3, ko = s - ec * 3;
            unsigned mb = (s & 1) ? mbarB1 : mbarB0;
            mbar_expect_tx(mb, B_BYTES);
            const unsigned* src =
                g_Bw + ((size_t)nt * KP_TOT + ko * 160 + ec * 16) * 80;
            cp_bulk(Bsm + (s & 1) * B_STG, src, B_BYTES, mb);
        }
    };

    float c[4][5][4];
#pragma unroll
    for (int i = 0; i < 4; i++)
#pragma unroll
        for (int j = 0; j < 5; j++)
#pragma unroll
            for (int k = 0; k < 4; k++) c[i][j][k] = 0.0f;

    prefetch_E(0);
    prefetch_B(0);

    for (int s = 0; s < C_STEPS; s++) {
        const int ec = s / 3, ko = s - ec * 3;
        const int ebs = ec & 1, bbs = s & 1;

        mbar_wait(bbs ? mbarB1 : mbarB0, (s >> 1) & 1);
        if (ko == 0) CP_WAIT0();
        __syncthreads();

        if (ko == 0 && ec + 1 < C_NCH) prefetch_E(ec + 1);
        if (s + 1 < C_STEPS) prefetch_B(s + 1);

        const unsigned* Eb = E + ebs * E_BUF;
        const unsigned* Bk = Bsm + bbs * B_STG;

#pragma unroll
        for (int kb = 0; kb < 2; kb++) {
            int kk = kb * 8;
            unsigned a[4][4];
#pragma unroll
            for (int ms = 0; ms < 4; ms++) {
                int row = mwb + ms * 16 + g + ko;
                a[ms][0] = Eb[(row)     * E_PITCH + kk + tig];
                a[ms][1] = Eb[(row + 8) * E_PITCH + kk + tig];
                a[ms][2] = Eb[(row)     * E_PITCH + kk + tig + 4];
                a[ms][3] = Eb[(row + 8) * E_PITCH + kk + tig + 4];
            }
#pragma unroll
            for (int ns = 0; ns < 5; ns++) {
                unsigned bf[2];
                int nb = nwb + ns * 8 + g;
                bf[0] = Bk[(kk + tig)     * B_PITCH + nb];
                bf[1] = Bk[(kk + tig + 4) * B_PITCH + nb];
#pragma unroll
                for (int ms = 0; ms < 4; ms++)
                    mma16(c[ms][ns], a[ms], bf);
            }
        }
    }

#pragma unroll
    for (int ms = 0; ms < 4; ms++) {
#pragma unroll
        for (int ns = 0; ns < 5; ns++) {
            int col = n0 + nwb + ns * 8 + 2 * tig;
            float2 bias = *(const float2*)&cb[col];
            int row0 = t0 + mwb + ms * 16 + g;
            *(float2*)&dst[((size_t)b * L + row0) * FILT + col] =
                make_float2(c[ms][ns][0] + bias.x, c[ms][ns][1] + bias.y);
            *(float2*)&dst[((size_t)b * L + row0 + 8) * FILT + col] =
                make_float2(c[ms][ns][2] + bias.x, c[ms][ns][3] + bias.y);
        }
    }
}

// ---------------------------------------------------------------------------
// 2) T = Qm @ W : tf32, 128 thr, warp 64x40, 2-stage cp.async (hidden under convA)
// ---------------------------------------------------------------------------
#define T_KC 40
#define T_AP 44
#define T_BP 88
#define T_ABUF (128 * T_AP)
#define T_BOFF (2 * T_ABUF)
#define T_BBUF (T_KC * T_BP)
#define SMEM_T ((T_BOFF + 2 * T_BBUF) * 4)

__global__ __launch_bounds__(128, 2) void gemm_T_kernel(const float* __restrict__ W)
{
    extern __shared__ unsigned sm[];
    unsigned* Asm = sm;
    unsigned* Bsm = sm + T_BOFF;

    const int b  = blockIdx.z;
    const int n0 = blockIdx.x * 80;
    const int tid  = threadIdx.x;
    const int wid  = tid >> 5, lane = tid & 31;
    const int g    = lane >> 2, tig = lane & 3;
    const int wm   = wid & 1,  wn  = wid >> 1;
    const int mwb  = wm * 64, nwb = wn * 40;

    const float* Qb = g_Q + (size_t)b * LQv * FILT;

    auto prefetch = [&](int ch, int bs) {
        int k0 = ch * T_KC;
        unsigned* Ab = Asm + bs * T_ABUF;
        unsigned* Bb = Bsm + bs * T_BBUF;
#pragma unroll
        for (int it = 0; it < 10; it++) {
            int i = tid + it * 128;
            int m = i / 10, k4 = i - m * 10;
            cp16g(&Ab[m * T_AP + k4 * 4], Qb + (size_t)m * FILT + k0 + k4 * 4);
        }
        for (int i = tid; i < T_KC * 20; i += 128) {
            int kc = i / 20, sg = i - kc * 20;
            cp16g(&Bb[kc * T_BP + sg * 4], W + (size_t)(k0 + kc) * FILT + n0 + sg * 4);
        }
    };

    float c[4][5][4];
#pragma unroll
    for (int i = 0; i < 4; i++)
#pragma unroll
        for (int j = 0; j < 5; j++)
#pragma unroll
            for (int k = 0; k < 4; k++) c[i][j][k] = 0.0f;

    prefetch(0, 0);
    CP_COMMIT();

    for (int ch = 0; ch < FILT / T_KC; ch++) {
        int bs = ch & 1;
        if (ch + 1 < FILT / T_KC) prefetch(ch + 1, bs ^ 1);
        CP_COMMIT();
        CP_WAIT1();
        __syncthreads();

        const unsigned* Ab = Asm + bs * T_ABUF;
        const unsigned* Bb = Bsm + bs * T_BBUF;

#pragma unroll
        for (int kb = 0; kb < T_KC / 8; kb++) {
            int kk = kb * 8;
            unsigned a[4][4];
#pragma unroll
            for (int ms = 0; ms < 4; ms++) {
                int row = mwb + ms * 16 + g;
                a[ms][0] = Ab[(row)     * T_AP + kk + tig];
                a[ms][1] = Ab[(row + 8) * T_AP + kk + tig];
                a[ms][2] = Ab[(row)     * T_AP + kk + tig + 4];
                a[ms][3] = Ab[(row + 8) * T_AP + kk + tig + 4];
            }
#pragma unroll
            for (int ns = 0; ns < 5; ns++) {
                unsigned bf[2];
                int nb = nwb + ns * 8 + g;
                bf[0] = Bb[(kk + tig)     * T_BP + nb];
                bf[1] = Bb[(kk + tig + 4) * T_BP + nb];
#pragma unroll
                for (int ms = 0; ms < 4; ms++)
                    mma8(c[ms][ns], a[ms], bf);
            }
        }
        __syncthreads();
    }

#pragma unroll
    for (int ms = 0; ms < 4; ms++) {
#pragma unroll
        for (int ns = 0; ns < 5; ns++) {
            int col = n0 + nwb + ns * 8 + 2 * tig;
            int row0 = mwb + ms * 16 + g;
            *(float2*)&g_T[((size_t)b * LQv + row0) * FILT + col] =
                make_float2(c[ms][ns][0], c[ms][ns][1]);
            *(float2*)&g_T[((size_t)b * LQv + row0 + 8) * FILT + col] =
                make_float2(c[ms][ns][2], c[ms][ns][3]);
        }
    }
}

// ---------------------------------------------------------------------------
// 3) G = tanh(T @ A^T) fused maxes: tf32, 256 thr, warp 64x32, block 128x128,
//    2-stage cp.async.bulk + mbarrier
// ---------------------------------------------------------------------------
#define G_KC 40
#define G_AP 44
#define G_ABUF (128 * G_AP)
#define G_BOFF (2 * G_ABUF)
#define G_BBUF (128 * G_AP)
#define G_RED  (G_BOFF + 2 * G_BBUF)
#define G_MBAR (G_RED + 256)
#define SMEM_G ((G_MBAR + 8) * 4)
#define G_ROW_BYTES (G_KC * 4)    // 160

__global__ __launch_bounds__(256, 2) void gemm_G_kernel()
{
    extern __shared__ unsigned sm[];
    unsigned* Asm  = sm;
    unsigned* Bsm  = sm + G_BOFF;
    unsigned* srow = sm + G_RED;
    unsigned* scol = sm + G_RED + 128;

    const int b  = blockIdx.y;
    const int a0 = blockIdx.x * 128;
    const int tid  = threadIdx.x;
    const int wid  = tid >> 5, lane = tid & 31;
    const int g    = lane >> 2, tig = lane & 3;
    const int wm   = wid & 1,  wn  = wid >> 1;
    const int mwb  = wm * 64, nwb = wn * 32;

    const unsigned smem_base = smem_u32(sm);
    const unsigned mbar0 = smem_base + G_MBAR * 4;
    const unsigned mbar1 = smem_base + (G_MBAR + 2) * 4;

    if (tid == 0) { mbar_init(mbar0, 1); mbar_init(mbar1, 1); }
    if (tid < 128) { srow[tid] = enc_f(-2.0f); scol[tid] = enc_f(-2.0f); }
    __syncthreads();

    const float* Tb  = g_T + (size_t)b * LQv * FILT;
    const float* Ab0 = g_A + ((size_t)b * LAv + a0) * FILT;

    auto prefetch = [&](int ch, int bs) {
        int k0 = ch * G_KC;
        unsigned mb = bs ? mbar1 : mbar0;
        if (tid == 0) mbar_expect_tx(mb, 256 * G_ROW_BYTES);
        if (tid < 128) {
            cp_bulk(&(Asm + bs * G_ABUF)[tid * G_AP],
                    Tb + (size_t)tid * FILT + k0, G_ROW_BYTES, mb);
        } else {
            int n = tid - 128;
            cp_bulk(&(Bsm + bs * G_BBUF)[n * G_AP],
                    Ab0 + (size_t)n * FILT + k0, G_ROW_BYTES, mb);
        }
    };

    float c[4][4][4];
#pragma unroll
    for (int i = 0; i < 4; i++)
#pragma unroll
        for (int j = 0; j < 4; j++)
#pragma unroll
            for (int k = 0; k < 4; k++) c[i][j][k] = 0.0f;

    prefetch(0, 0);

    for (int ch = 0; ch < FILT / G_KC; ch++) {
        int bs = ch & 1;
        if (ch + 1 < FILT / G_KC) prefetch(ch + 1, bs ^ 1);
        mbar_wait(bs ? mbar1 : mbar0, (ch >> 1) & 1);
        __syncthreads();

        const unsigned* Abuf = Asm + bs * G_ABUF;
        const unsigned* Bbuf = Bsm + bs * G_BBUF;

#pragma unroll
        for (int kb = 0; kb < G_KC / 8; kb++) {
            int kk = kb * 8;
            unsigned a[4][4];
#pragma unroll
            for (int ms = 0; ms < 4; ms++) {
                int row = mwb + ms * 16 + g;
                a[ms][0] = Abuf[(row)     * G_AP + kk + tig];
                a[ms][1] = Abuf[(row + 8) * G_AP + kk + tig];
                a[ms][2] = Abuf[(row)     * G_AP + kk + tig + 4];
                a[ms][3] = Abuf[(row + 8) * G_AP + kk + tig + 4];
            }
#pragma unroll
            for (int ns = 0; ns < 4; ns++) {
                unsigned bf[2];
                int nb = nwb + ns * 8 + g;
                bf[0] = Bbuf[nb * G_AP + kk + tig];
                bf[1] = Bbuf[nb * G_AP + kk + tig + 4];
#pragma unroll
                for (int ms = 0; ms < 4; ms++)
                    mma8(c[ms][ns], a[ms], bf);
            }
        }
        __syncthreads();
    }

#pragma unroll
    for (int ms = 0; ms < 4; ms++) {
        float r0 = -2.0f, r1 = -2.0f;
#pragma unroll
        for (int ns = 0; ns < 4; ns++) {
#pragma unroll
            for (int k = 0; k < 4; k++) c[ms][ns][k] = tanhf(c[ms][ns][k]);
            r0 = fmaxf(r0, fmaxf(c[ms][ns][0], c[ms][ns][1]));
            r1 = fmaxf(r1, fmaxf(c[ms][ns][2], c[ms][ns][3]));
        }
        atomicMax(&srow[mwb + ms * 16 + g],     enc_f(r0));
        atomicMax(&srow[mwb + ms * 16 + g + 8], enc_f(r1));
    }
#pragma unroll
    for (int ns = 0; ns < 4; ns++) {
        float c0 = -2.0f, c1 = -2.0f;
#pragma unroll
        for (int ms = 0; ms < 4; ms++) {
            c0 = fmaxf(c0, fmaxf(c[ms][ns][0], c[ms][ns][2]));
            c1 = fmaxf(c1, fmaxf(c[ms][ns][1], c[ms][ns][3]));
        }
        int nb = nwb + ns * 8 + 2 * tig;
        atomicMax(&scol[nb],     enc_f(c0));
        atomicMax(&scol[nb + 1], enc_f(c1));
    }
    __syncthreads();

    if (tid < 128) {
        atomicMax(&g_mq[b * LQv + tid], srow[tid]);
        atomicMax(&g_ma[b * LAv + a0 + tid], scol[tid]);
    }
}

// ---------------------------------------------------------------------------
// 4a) per-batch softmax; writes normalized weights back into g_mq / g_ma
// ---------------------------------------------------------------------------
__device__ __forceinline__ float warp_max(float v) {
#pragma unroll
    for (int o = 16; o > 0; o >>= 1) v = fmaxf(v, __shfl_xor_sync(0xffffffffu, v, o));
    return v;
}
__device__ __forceinline__ float warp_sum(float v) {
#pragma unroll
    for (int o = 16; o > 0; o >>= 1) v += __shfl_xor_sync(0xffffffffu, v, o);
    return v;
}

__global__ __launch_bounds__(256) void softmax_kernel()
{
    __shared__ float sq[LQv], sa[LAv];
    __shared__ float smax[2], ssum[2];

    const int b = blockIdx.x;
    const int tid = threadIdx.x;
    const int lane = tid & 31;

    for (int q = tid; q < LQv; q += 256) sq[q] = dec_f(g_mq[b * LQv + q]);
    for (int a = tid; a < LAv; a += 256) sa[a] = dec_f(g_ma[b * LAv + a]);
    __syncthreads();

    if (tid < 32) {
        float m = -1e30f;
        for (int q = lane; q < LQv; q += 32) m = fmaxf(m, sq[q]);
        m = warp_max(m);
        if (lane == 0) smax[0] = m;
    } else if (tid < 64) {
        float m = -1e30f;
        for (int a = lane; a < LAv; a += 32) m = fmaxf(m, sa[a]);
        m = warp_max(m);
        if (lane == 0) smax[1] = m;
    }
    __syncthreads();
    for (int q = tid; q < LQv; q += 256) sq[q] = expf(sq[q] - smax[0]);
    for (int a = tid; a < LAv; a += 256) sa[a] = expf(sa[a] - smax[1]);
    __syncthreads();
    if (tid < 32) {
        float s = 0.0f;
        for (int q = lane; q < LQv; q += 32) s += sq[q];
        s = warp_sum(s);
        if (lane == 0) ssum[0] = s;
    } else if (tid < 64) {
        float s = 0.0f;
        for (int a = lane; a < LAv; a += 32) s += sa[a];
        s = warp_sum(s);
        if (lane == 0) ssum[1] = s;
    }
    __syncthreads();
    float invq = 1.0f / ssum[0], inva = 1.0f / ssum[1];
    for (int q = tid; q < LQv; q += 256)
        g_mq[b * LQv + q] = __float_as_uint(sq[q] * invq);
    for (int a = tid; a < LAv; a += 256)
        g_ma[b * LAv + a] = __float_as_uint(sa[a] * inva);
}

// ---------------------------------------------------------------------------
// 4b) pooling partials: grid (128 b, 2 halves), 256 thr, 200 f each
// ---------------------------------------------------------------------------
__global__ __launch_bounds__(256) void pool_kernel()
{
    __shared__ float wq[LQv], wa[LAv];
    __shared__ float rd[256], rx[256], ry[256];

    const int b = blockIdx.x;
    const int f0 = blockIdx.y * 200;
    const int tid = threadIdx.x;

    for (int q = tid; q < LQv; q += 256) wq[q] = __uint_as_float(g_mq[b * LQv + q]);
    for (int a = tid; a < LAv; a += 256) wa[a] = __uint_as_float(g_ma[b * LAv + a]);
    __syncthreads();

    float d = 0.0f, x = 0.0f, y = 0.0f;
    if (tid < 200) {
        int f = f0 + tid;
        const float* qp = g_Q + (size_t)b * LQv * FILT + f;
        float accq = 0.0f;
#pragma unroll 8
        for (int q = 0; q < LQv; q++) accq += qp[(size_t)q * FILT] * wq[q];
        const float* ap = g_A + (size_t)b * LAv * FILT + f;
        float acca = 0.0f;
#pragma unroll 8
        for (int a = 0; a < LAv; a++) acca += ap[(size_t)a * FILT] * wa[a];
        d = accq * acca; x = accq * accq; y = acca * acca;
    }
    rd[tid] = d; rx[tid] = x; ry[tid] = y;
    __syncthreads();
#pragma unroll
    for (int s = 128; s > 0; s >>= 1) {
        if (tid < s) {
            rd[tid] += rd[tid + s];
            rx[tid] += rx[tid + s];
            ry[tid] += ry[tid + s];
        }
        __syncthreads();
    }
    if (tid == 0) {
        atomicAdd(&g_dxy[b * 4 + 0], rd[0]);
        atomicAdd(&g_dxy[b * 4 + 1], rx[0]);
        atomicAdd(&g_dxy[b * 4 + 2], ry[0]);
    }
}

// ---------------------------------------------------------------------------
// 4c) final cosine
// ---------------------------------------------------------------------------
__global__ __launch_bounds__(128) void final_out_kernel(float* __restrict__ out)
{
    int b = threadIdx.x;
    float D = g_dxy[b * 4 + 0];
    float X = g_dxy[b * 4 + 1];
    float Y = g_dxy[b * 4 + 2];
    float nq = fmaxf(sqrtf(X), 1e-8f);
    float na = fmaxf(sqrtf(Y), 1e-8f);
    out[b] = D / (nq * na);
}

// ---------------------------------------------------------------------------
// launch — two streams: convA on s2 overlaps convQ + gemm_T on main
// ---------------------------------------------------------------------------
extern "C" void kernel_launch(void* const* d_in, const int* in_sizes, int n_in,
                              void* d_out, int out_size)
{
    const int*   questions = (const int*)d_in[0];
    const int*   answers   = (const int*)d_in[1];
    const float* emb       = (const float*)d_in[2];
    const float* conv_w    = (const float*)d_in[3];
    const float* conv_b    = (const float*)d_in[4];
    const float* W         = (const float*)d_in[5];
    float*       out       = (float*)d_out;

    (void)in_sizes; (void)n_in; (void)out_size;

    static bool init_done = false;
    static cudaStream_t s2;
    static cudaEvent_t evFork, evJoin;
    if (!init_done) {
        cudaFuncSetAttribute(conv_encode_kernel,
                             cudaFuncAttributeMaxDynamicSharedMemorySize, SMEM_CONV);
        cudaFuncSetAttribute(gemm_T_kernel,
                             cudaFuncAttributeMaxDynamicSharedMemorySize, SMEM_T);
        cudaFuncSetAttribute(gemm_G_kernel,
                             cudaFuncAttributeMaxDynamicSharedMemorySize, SMEM_G);
        cudaStreamCreateWithFlags(&s2, cudaStreamNonBlocking);
        cudaEventCreateWithFlags(&evFork, cudaEventDisableTiming);
        cudaEventCreateWithFlags(&evJoin, cudaEventDisableTiming);
        init_done = true;
    }

    init_max_kernel<<<(BATCH * LAv + 255) / 256, 256>>>();
    transpose_w_kernel<<<(5 * KP_TOT * 80 + 255) / 256, 256>>>(conv_w);
    emb_cvt_kernel<<<(int)(((size_t)VROWS * 160 + 255) / 256), 256>>>(emb);

    // fork: convA on s2 after prologue
    cudaEventRecord(evFork, 0);
    cudaStreamWaitEvent(s2, evFork, 0);

    conv_encode_kernel<<<dim3(4, 5, BATCH), 128, SMEM_CONV, s2>>>(
        questions, answers, conv_b, 0);   // answers

    // main stream: convQ then T (Q-only dependency)
    conv_encode_kernel<<<dim3(1, 5, BATCH), 128, SMEM_CONV>>>(
        questions, answers, conv_b, 1);   // questions
    gemm_T_kernel<<<dim3(FILT / 80, 1, BATCH), 128, SMEM_T>>>(W);

    // join: G needs A (s2) and T (main)
    cudaEventRecord(evJoin, s2);
    cudaStreamWaitEvent(0, evJoin, 0);

    gemm_G_kernel<<<dim3(LAv / 128, BATCH), 256, SMEM_G>>>();

    softmax_kernel<<<BATCH, 256>>>();
    pool_kernel<<<dim3(BATCH, 2), 256>>>();
    final_out_kernel<<<1, 128>>>(out);
}

// round 14
// speedup vs baseline: 1.3200x; 1.0263x over previous
#include <cuda_runtime.h>
#include <cuda_bf16.h>
#include <math.h>

#define BATCH 128
#define LQv   128
#define LAv   512
#define EMBD  300
#define FILT  400
#define VROWS 50001
#define KP_TOT 480            // 3 koff * 160 kp
#define FPW   200             // FILT/2 words per packed row

// ---- scratch (static __device__: no allocations allowed) ----
__device__ float    g_Q[BATCH * LQv * FILT];
__device__ float    g_A[BATCH * LAv * FILT];
__device__ unsigned g_Abf[(size_t)BATCH * LAv * FPW];  // bf16-pair A for G
__device__ unsigned g_Tbf[(size_t)BATCH * LQv * FPW];  // bf16-pair T for G
__device__ unsigned g_Bw[5 * KP_TOT * 80];             // bf16-pair conv weights
__device__ unsigned g_Ebf[(size_t)VROWS * 160];        // bf16-pair padded emb
__device__ unsigned g_mq[BATCH * LQv];
__device__ unsigned g_ma[BATCH * LAv];
__device__ float    g_dxy[BATCH * 4];

__device__ __forceinline__ unsigned enc_f(float f) {
    int i = __float_as_int(f);
    return (unsigned)(i ^ ((i >> 31) | 0x80000000));
}
__device__ __forceinline__ float dec_f(unsigned u) {
    int i = (u & 0x80000000u) ? (int)(u ^ 0x80000000u) : ~(int)u;
    return __int_as_float(i);
}
__device__ __forceinline__ unsigned pack_bf2(float lo, float hi) {
    unsigned short l = __bfloat16_as_ushort(__float2bfloat16(lo));
    unsigned short h = __bfloat16_as_ushort(__float2bfloat16(hi));
    return (unsigned)l | ((unsigned)h << 16);
}
__device__ __forceinline__ void mma8(float* c, const unsigned* a, const unsigned* b) {
    asm("mma.sync.aligned.m16n8k8.row.col.f32.tf32.tf32.f32 "
        "{%0,%1,%2,%3},{%4,%5,%6,%7},{%8,%9},{%0,%1,%2,%3};"
        : "+f"(c[0]), "+f"(c[1]), "+f"(c[2]), "+f"(c[3])
        : "r"(a[0]), "r"(a[1]), "r"(a[2]), "r"(a[3]), "r"(b[0]), "r"(b[1]));
}
__device__ __forceinline__ void mma16(float* c, const unsigned* a, const unsigned* b) {
    asm("mma.sync.aligned.m16n8k16.row.col.f32.bf16.bf16.f32 "
        "{%0,%1,%2,%3},{%4,%5,%6,%7},{%8,%9},{%0,%1,%2,%3};"
        : "+f"(c[0]), "+f"(c[1]), "+f"(c[2]), "+f"(c[3])
        : "r"(a[0]), "r"(a[1]), "r"(a[2]), "r"(a[3]), "r"(b[0]), "r"(b[1]));
}
__device__ __forceinline__ void cp16g(void* sptr, const void* gptr) {
    unsigned s = (unsigned)__cvta_generic_to_shared(sptr);
    asm volatile("cp.async.cg.shared.global [%0], [%1], 16;"
                 :: "r"(s), "l"(gptr));
}
#define CP_COMMIT() asm volatile("cp.async.commit_group;")
#define CP_WAIT0()  asm volatile("cp.async.wait_group 0;")
#define CP_WAIT1()  asm volatile("cp.async.wait_group 1;")

// ---- mbarrier + bulk helpers ----
__device__ __forceinline__ void mbar_init(unsigned addr, unsigned count) {
    asm volatile("mbarrier.init.shared.b64 [%0], %1;" :: "r"(addr), "r"(count) : "memory");
}
__device__ __forceinline__ void mbar_expect_tx(unsigned addr, unsigned bytes) {
    asm volatile("mbarrier.arrive.expect_tx.shared.b64 _, [%0], %1;"
                 :: "r"(addr), "r"(bytes) : "memory");
}
__device__ __forceinline__ void mbar_wait(unsigned addr, unsigned phase) {
    unsigned done = 0;
    while (!done) {
        asm volatile(
            "{\n\t.reg .pred p;\n\t"
            "mbarrier.try_wait.parity.shared.b64 p, [%1], %2;\n\t"
            "selp.b32 %0, 1, 0, p;\n\t}"
            : "=r"(done) : "r"(addr), "r"(phase) : "memory");
    }
}
__device__ __forceinline__ void cp_bulk(void* sptr, const void* gptr,
                                        unsigned bytes, unsigned mbar) {
    unsigned s = (unsigned)__cvta_generic_to_shared(sptr);
    asm volatile(
        "cp.async.bulk.shared::cta.global.mbarrier::complete_tx::bytes "
        "[%0], [%1], %2, [%3];"
        :: "r"(s), "l"(gptr), "r"(bytes), "r"(mbar) : "memory");
}
__device__ __forceinline__ unsigned smem_u32(const void* p) {
    unsigned r;
    asm("{ .reg .u64 t; cvta.to.shared.u64 t, %1; cvt.u32.u64 %0, t; }"
        : "=r"(r) : "l"(p));
    return r;
}

// ---------------------------------------------------------------------------
// 0) init + weight pack + emb convert
// ---------------------------------------------------------------------------
__global__ void init_max_kernel() {
    int idx = blockIdx.x * blockDim.x + threadIdx.x;
    unsigned v = enc_f(-2.0f);
    if (idx < BATCH * LQv) g_mq[idx] = v;
    if (idx < BATCH * LAv) g_ma[idx] = v;
    if (idx < BATCH * 4)   g_dxy[idx] = 0.0f;
}

__global__ void transpose_w_kernel(const float* __restrict__ cw) {
    int idx = blockIdx.x * blockDim.x + threadIdx.x;
    if (idx >= 5 * KP_TOT * 80) return;
    int nt = idx / (KP_TOT * 80);
    int r  = idx - nt * (KP_TOT * 80);
    int kp = r / 80, nn = r - kp * 80;
    int n = nt * 80 + nn;
    int ko = kp / 160, ep = kp - ko * 160;
    int e0 = 2 * ep, e1 = 2 * ep + 1;
    float v0 = (e0 < EMBD) ? cw[(size_t)n * (EMBD * 3) + e0 * 3 + ko] : 0.0f;
    float v1 = (e1 < EMBD) ? cw[(size_t)n * (EMBD * 3) + e1 * 3 + ko] : 0.0f;
    g_Bw[idx] = pack_bf2(v0, v1);
}

__global__ void emb_cvt_kernel(const float* __restrict__ emb) {
    size_t idx = (size_t)blockIdx.x * blockDim.x + threadIdx.x;
    if (idx >= (size_t)VROWS * 160) return;
    int row = (int)(idx / 160), wp = (int)(idx - (size_t)row * 160);
    int e0 = 2 * wp, e1 = e0 + 1;
    float v0 = (e0 < EMBD) ? emb[(size_t)row * EMBD + e0] : 0.0f;
    float v1 = (e1 < EMBD) ? emb[(size_t)row * EMBD + e1] : 0.0f;
    g_Ebf[idx] = pack_bf2(v0, v1);
}

// ---------------------------------------------------------------------------
// 1) conv encode (bf16 m16n8k16), 128 thr, warp 64x40, block 128 tok x 80 f.
//    Dual-store epilogue: f32 always; bf16-packed for A (G's B-side).
// ---------------------------------------------------------------------------
#define C_NCH  10
#define C_STEPS 30
#define E_PITCH 20
#define E_BUF  (130 * E_PITCH)
#define B_PITCH 80
#define B_STG  (16 * B_PITCH)
#define B_BYTES (B_STG * 4)
#define SM_MBAR 136
#define SM_E_OFF 144
#define SM_B_OFF (SM_E_OFF + 2 * E_BUF)
#define SMEM_CONV ((SM_B_OFF + 2 * B_STG) * 4)

__global__ __launch_bounds__(128, 3) void conv_encode_kernel(
    const int* __restrict__ qtok, const int* __restrict__ atok,
    const float* __restrict__ cb, int is_q)
{
    extern __shared__ unsigned sm[];
    int*      s_tok = (int*)sm;
    unsigned* E     = sm + SM_E_OFF;
    unsigned* Bsm   = sm + SM_B_OFF;

    const int b   = blockIdx.z;
    const int nt  = blockIdx.y;
    const int n0  = nt * 80;
    const int tid = threadIdx.x;
    const int wid = tid >> 5, lane = tid & 31;
    const int g   = lane >> 2, tig = lane & 3;
    const int wm  = wid & 1,  wn  = wid >> 1;
    const int mwb = wm * 64,  nwb = wn * 40;

    const unsigned smem_base = smem_u32(sm);
    const unsigned mbarB0 = smem_base + SM_MBAR * 4;
    const unsigned mbarB1 = smem_base + (SM_MBAR + 2) * 4;

    const int* tok = is_q ? qtok : atok;
    float* dst     = is_q ? g_Q : g_A;
    const int L    = is_q ? LQv : LAv;
    const int t0   = blockIdx.x * 128;

    if (tid == 0) { mbar_init(mbarB0, 1); mbar_init(mbarB1, 1); }
    for (int r = tid; r < 130; r += 128) {
        int tg = t0 + r - 1;
        s_tok[r] = (tg >= 0 && tg < L) ? tok[b * L + tg] : 0;
    }
    __syncthreads();

    auto prefetch_E = [&](int ec) {
        unsigned* Eb = E + (ec & 1) * E_BUF;
        int w0 = ec * 16;
        for (int i = tid; i < 130 * 4; i += 128) {
            int r = i >> 2, sg = i & 3;
            cp16g(&Eb[r * E_PITCH + sg * 4],
                  g_Ebf + (size_t)s_tok[r] * 160 + w0 + sg * 4);
        }
        CP_COMMIT();
    };
    auto prefetch_B = [&](int s) {
        if (tid == 0) {
            int ec = s / 3, ko = s - ec * 3;
            unsigned mb = (s & 1) ? mbarB1 : mbarB0;
            mbar_expect_tx(mb, B_BYTES);
            const unsigned* src =
                g_Bw + ((size_t)nt * KP_TOT + ko * 160 + ec * 16) * 80;
            cp_bulk(Bsm + (s & 1) * B_STG, src, B_BYTES, mb);
        }
    };

    float c[4][5][4];
#pragma unroll
    for (int i = 0; i < 4; i++)
#pragma unroll
        for (int j = 0; j < 5; j++)
#pragma unroll
            for (int k = 0; k < 4; k++) c[i][j][k] = 0.0f;

    prefetch_E(0);
    prefetch_B(0);

    for (int s = 0; s < C_STEPS; s++) {
        const int ec = s / 3, ko = s - ec * 3;
        const int ebs = ec & 1, bbs = s & 1;

        mbar_wait(bbs ? mbarB1 : mbarB0, (s >> 1) & 1);
        if (ko == 0) CP_WAIT0();
        __syncthreads();

        if (ko == 0 && ec + 1 < C_NCH) prefetch_E(ec + 1);
        if (s + 1 < C_STEPS) prefetch_B(s + 1);

        const unsigned* Eb = E + ebs * E_BUF;
        const unsigned* Bk = Bsm + bbs * B_STG;

#pragma unroll
        for (int kb = 0; kb < 2; kb++) {
            int kk = kb * 8;
            unsigned a[4][4];
#pragma unroll
            for (int ms = 0; ms < 4; ms++) {
                int row = mwb + ms * 16 + g + ko;
                a[ms][0] = Eb[(row)     * E_PITCH + kk + tig];
                a[ms][1] = Eb[(row + 8) * E_PITCH + kk + tig];
                a[ms][2] = Eb[(row)     * E_PITCH + kk + tig + 4];
                a[ms][3] = Eb[(row + 8) * E_PITCH + kk + tig + 4];
            }
#pragma unroll
            for (int ns = 0; ns < 5; ns++) {
                unsigned bf[2];
                int nb = nwb + ns * 8 + g;
                bf[0] = Bk[(kk + tig)     * B_PITCH + nb];
                bf[1] = Bk[(kk + tig + 4) * B_PITCH + nb];
#pragma unroll
                for (int ms = 0; ms < 4; ms++)
                    mma16(c[ms][ns], a[ms], bf);
            }
        }
    }

#pragma unroll
    for (int ms = 0; ms < 4; ms++) {
#pragma unroll
        for (int ns = 0; ns < 5; ns++) {
            int col = n0 + nwb + ns * 8 + 2 * tig;
            float2 bias = *(const float2*)&cb[col];
            int row0 = t0 + mwb + ms * 16 + g;
            float v0 = c[ms][ns][0] + bias.x, v1 = c[ms][ns][1] + bias.y;
            float v2 = c[ms][ns][2] + bias.x, v3 = c[ms][ns][3] + bias.y;
            *(float2*)&dst[((size_t)b * L + row0) * FILT + col] = make_float2(v0, v1);
            *(float2*)&dst[((size_t)b * L + row0 + 8) * FILT + col] = make_float2(v2, v3);
            if (!is_q) {
                g_Abf[((size_t)b * LAv + row0) * FPW + (col >> 1)] = pack_bf2(v0, v1);
                g_Abf[((size_t)b * LAv + row0 + 8) * FPW + (col >> 1)] = pack_bf2(v2, v3);
            }
        }
    }
}

// ---------------------------------------------------------------------------
// 2) T = Qm @ W : tf32 compute (hidden under convA), bf16-packed output
// ---------------------------------------------------------------------------
#define T_KC 40
#define T_AP 44
#define T_BP 88
#define T_ABUF (128 * T_AP)
#define T_BOFF (2 * T_ABUF)
#define T_BBUF (T_KC * T_BP)
#define SMEM_T ((T_BOFF + 2 * T_BBUF) * 4)

__global__ __launch_bounds__(128, 2) void gemm_T_kernel(const float* __restrict__ W)
{
    extern __shared__ unsigned sm[];
    unsigned* Asm = sm;
    unsigned* Bsm = sm + T_BOFF;

    const int b  = blockIdx.z;
    const int n0 = blockIdx.x * 80;
    const int tid  = threadIdx.x;
    const int wid  = tid >> 5, lane = tid & 31;
    const int g    = lane >> 2, tig = lane & 3;
    const int wm   = wid & 1,  wn  = wid >> 1;
    const int mwb  = wm * 64, nwb = wn * 40;

    const float* Qb = g_Q + (size_t)b * LQv * FILT;

    auto prefetch = [&](int ch, int bs) {
        int k0 = ch * T_KC;
        unsigned* Ab = Asm + bs * T_ABUF;
        unsigned* Bb = Bsm + bs * T_BBUF;
#pragma unroll
        for (int it = 0; it < 10; it++) {
            int i = tid + it * 128;
            int m = i / 10, k4 = i - m * 10;
            cp16g(&Ab[m * T_AP + k4 * 4], Qb + (size_t)m * FILT + k0 + k4 * 4);
        }
        for (int i = tid; i < T_KC * 20; i += 128) {
            int kc = i / 20, sg = i - kc * 20;
            cp16g(&Bb[kc * T_BP + sg * 4], W + (size_t)(k0 + kc) * FILT + n0 + sg * 4);
        }
    };

    float c[4][5][4];
#pragma unroll
    for (int i = 0; i < 4; i++)
#pragma unroll
        for (int j = 0; j < 5; j++)
#pragma unroll
            for (int k = 0; k < 4; k++) c[i][j][k] = 0.0f;

    prefetch(0, 0);
    CP_COMMIT();

    for (int ch = 0; ch < FILT / T_KC; ch++) {
        int bs = ch & 1;
        if (ch + 1 < FILT / T_KC) prefetch(ch + 1, bs ^ 1);
        CP_COMMIT();
        CP_WAIT1();
        __syncthreads();

        const unsigned* Ab = Asm + bs * T_ABUF;
        const unsigned* Bb = Bsm + bs * T_BBUF;

#pragma unroll
        for (int kb = 0; kb < T_KC / 8; kb++) {
            int kk = kb * 8;
            unsigned a[4][4];
#pragma unroll
            for (int ms = 0; ms < 4; ms++) {
                int row = mwb + ms * 16 + g;
                a[ms][0] = Ab[(row)     * T_AP + kk + tig];
                a[ms][1] = Ab[(row + 8) * T_AP + kk + tig];
                a[ms][2] = Ab[(row)     * T_AP + kk + tig + 4];
                a[ms][3] = Ab[(row + 8) * T_AP + kk + tig + 4];
            }
#pragma unroll
            for (int ns = 0; ns < 5; ns++) {
                unsigned bf[2];
                int nb = nwb + ns * 8 + g;
                bf[0] = Bb[(kk + tig)     * T_BP + nb];
                bf[1] = Bb[(kk + tig + 4) * T_BP + nb];
#pragma unroll
                for (int ms = 0; ms < 4; ms++)
                    mma8(c[ms][ns], a[ms], bf);
            }
        }
        __syncthreads();
    }

#pragma unroll
    for (int ms = 0; ms < 4; ms++) {
#pragma unroll
        for (int ns = 0; ns < 5; ns++) {
            int col = n0 + nwb + ns * 8 + 2 * tig;
            int row0 = mwb + ms * 16 + g;
            g_Tbf[((size_t)b * LQv + row0) * FPW + (col >> 1)] =
                pack_bf2(c[ms][ns][0], c[ms][ns][1]);
            g_Tbf[((size_t)b * LQv + row0 + 8) * FPW + (col >> 1)] =
                pack_bf2(c[ms][ns][2], c[ms][ns][3]);
        }
    }
}

// ---------------------------------------------------------------------------
// 3) G = tanh(T @ A^T) fused maxes: bf16 m16n8k16, 256 thr, warp 64x32,
//    block 128 x 128, 5 K-chunks of 40 words, bulk + mbarrier pipeline
// ---------------------------------------------------------------------------
#define G_KW 40                   // words per chunk (80 elements)
#define G_AP 44
#define G_ABUF (128 * G_AP)
#define G_BOFF (2 * G_ABUF)
#define G_BBUF (128 * G_AP)
#define G_RED  (G_BOFF + 2 * G_BBUF)
#define G_MBAR (G_RED + 256)
#define SMEM_G ((G_MBAR + 8) * 4)
#define G_ROW_BYTES (G_KW * 4)    // 160

__global__ __launch_bounds__(256, 2) void gemm_G_kernel()
{
    extern __shared__ unsigned sm[];
    unsigned* Asm  = sm;
    unsigned* Bsm  = sm + G_BOFF;
    unsigned* srow = sm + G_RED;
    unsigned* scol = sm + G_RED + 128;

    const int b  = blockIdx.y;
    const int a0 = blockIdx.x * 128;
    const int tid  = threadIdx.x;
    const int wid  = tid >> 5, lane = tid & 31;
    const int g    = lane >> 2, tig = lane & 3;
    const int wm   = wid & 1,  wn  = wid >> 1;
    const int mwb  = wm * 64, nwb = wn * 32;

    const unsigned smem_base = smem_u32(sm);
    const unsigned mbar0 = smem_base + G_MBAR * 4;
    const unsigned mbar1 = smem_base + (G_MBAR + 2) * 4;

    if (tid == 0) { mbar_init(mbar0, 1); mbar_init(mbar1, 1); }
    if (tid < 128) { srow[tid] = enc_f(-2.0f); scol[tid] = enc_f(-2.0f); }
    __syncthreads();

    const unsigned* Tb  = g_Tbf + (size_t)b * LQv * FPW;
    const unsigned* Ab0 = g_Abf + ((size_t)b * LAv + a0) * FPW;

    auto prefetch = [&](int ch, int bs) {
        int k0 = ch * G_KW;
        unsigned mb = bs ? mbar1 : mbar0;
        if (tid == 0) mbar_expect_tx(mb, 256 * G_ROW_BYTES);
        if (tid < 128) {
            cp_bulk(&(Asm + bs * G_ABUF)[tid * G_AP],
                    Tb + (size_t)tid * FPW + k0, G_ROW_BYTES, mb);
        } else {
            int n = tid - 128;
            cp_bulk(&(Bsm + bs * G_BBUF)[n * G_AP],
                    Ab0 + (size_t)n * FPW + k0, G_ROW_BYTES, mb);
        }
    };

    float c[4][4][4];
#pragma unroll
    for (int i = 0; i < 4; i++)
#pragma unroll
        for (int j = 0; j < 4; j++)
#pragma unroll
            for (int k = 0; k < 4; k++) c[i][j][k] = 0.0f;

    prefetch(0, 0);

    for (int ch = 0; ch < 5; ch++) {
        int bs = ch & 1;
        if (ch + 1 < 5) prefetch(ch + 1, bs ^ 1);
        mbar_wait(bs ? mbar1 : mbar0, (ch >> 1) & 1);
        __syncthreads();

        const unsigned* Abuf = Asm + bs * G_ABUF;
        const unsigned* Bbuf = Bsm + bs * G_BBUF;

#pragma unroll
        for (int kb = 0; kb < 5; kb++) {
            int kk = kb * 8;
            unsigned a[4][4];
#pragma unroll
            for (int ms = 0; ms < 4; ms++) {
                int row = mwb + ms * 16 + g;
                a[ms][0] = Abuf[(row)     * G_AP + kk + tig];
                a[ms][1] = Abuf[(row + 8) * G_AP + kk + tig];
                a[ms][2] = Abuf[(row)     * G_AP + kk + tig + 4];
                a[ms][3] = Abuf[(row + 8) * G_AP + kk + tig + 4];
            }
#pragma unroll
            for (int ns = 0; ns < 4; ns++) {
                unsigned bf[2];
                int nb = nwb + ns * 8 + g;
                bf[0] = Bbuf[nb * G_AP + kk + tig];
                bf[1] = Bbuf[nb * G_AP + kk + tig + 4];
#pragma unroll
                for (int ms = 0; ms < 4; ms++)
                    mma16(c[ms][ns], a[ms], bf);
            }
        }
        __syncthreads();
    }

#pragma unroll
    for (int ms = 0; ms < 4; ms++) {
        float r0 = -2.0f, r1 = -2.0f;
#pragma unroll
        for (int ns = 0; ns < 4; ns++) {
#pragma unroll
            for (int k = 0; k < 4; k++) c[ms][ns][k] = tanhf(c[ms][ns][k]);
            r0 = fmaxf(r0, fmaxf(c[ms][ns][0], c[ms][ns][1]));
            r1 = fmaxf(r1, fmaxf(c[ms][ns][2], c[ms][ns][3]));
        }
        atomicMax(&srow[mwb + ms * 16 + g],     enc_f(r0));
        atomicMax(&srow[mwb + ms * 16 + g + 8], enc_f(r1));
    }
#pragma unroll
    for (int ns = 0; ns < 4; ns++) {
        float c0 = -2.0f, c1 = -2.0f;
#pragma unroll
        for (int ms = 0; ms < 4; ms++) {
            c0 = fmaxf(c0, fmaxf(c[ms][ns][0], c[ms][ns][2]));
            c1 = fmaxf(c1, fmaxf(c[ms][ns][1], c[ms][ns][3]));
        }
        int nb = nwb + ns * 8 + 2 * tig;
        atomicMax(&scol[nb],     enc_f(c0));
        atomicMax(&scol[nb + 1], enc_f(c1));
    }
    __syncthreads();

    if (tid < 128) {
        atomicMax(&g_mq[b * LQv + tid], srow[tid]);
        atomicMax(&g_ma[b * LAv + a0 + tid], scol[tid]);
    }
}

// ---------------------------------------------------------------------------
// 4a) per-batch softmax; writes normalized weights back into g_mq / g_ma
// ---------------------------------------------------------------------------
__device__ __forceinline__ float warp_max(float v) {
#pragma unroll
    for (int o = 16; o > 0; o >>= 1) v = fmaxf(v, __shfl_xor_sync(0xffffffffu, v, o));
    return v;
}
__device__ __forceinline__ float warp_sum(float v) {
#pragma unroll
    for (int o = 16; o > 0; o >>= 1) v += __shfl_xor_sync(0xffffffffu, v, o);
    return v;
}

__global__ __launch_bounds__(256) void softmax_kernel()
{
    __shared__ float sq[LQv], sa[LAv];
    __shared__ float smax[2], ssum[2];

    const int b = blockIdx.x;
    const int tid = threadIdx.x;
    const int lane = tid & 31;

    for (int q = tid; q < LQv; q += 256) sq[q] = dec_f(g_mq[b * LQv + q]);
    for (int a = tid; a < LAv; a += 256) sa[a] = dec_f(g_ma[b * LAv + a]);
    __syncthreads();

    if (tid < 32) {
        float m = -1e30f;
        for (int q = lane; q < LQv; q += 32) m = fmaxf(m, sq[q]);
        m = warp_max(m);
        if (lane == 0) smax[0] = m;
    } else if (tid < 64) {
        float m = -1e30f;
        for (int a = lane; a < LAv; a += 32) m = fmaxf(m, sa[a]);
        m = warp_max(m);
        if (lane == 0) smax[1] = m;
    }
    __syncthreads();
    for (int q = tid; q < LQv; q += 256) sq[q] = expf(sq[q] - smax[0]);
    for (int a = tid; a < LAv; a += 256) sa[a] = expf(sa[a] - smax[1]);
    __syncthreads();
    if (tid < 32) {
        float s = 0.0f;
        for (int q = lane; q < LQv; q += 32) s += sq[q];
        s = warp_sum(s);
        if (lane == 0) ssum[0] = s;
    } else if (tid < 64) {
        float s = 0.0f;
        for (int a = lane; a < LAv; a += 32) s += sa[a];
        s = warp_sum(s);
        if (lane == 0) ssum[1] = s;
    }
    __syncthreads();
    float invq = 1.0f / ssum[0], inva = 1.0f / ssum[1];
    for (int q = tid; q < LQv; q += 256)
        g_mq[b * LQv + q] = __float_as_uint(sq[q] * invq);
    for (int a = tid; a < LAv; a += 256)
        g_ma[b * LAv + a] = __float_as_uint(sa[a] * inva);
}

// ---------------------------------------------------------------------------
// 4b) pooling partials: grid (128 b, 2 halves), 256 thr, 200 f each
// ---------------------------------------------------------------------------
__global__ __launch_bounds__(256) void pool_kernel()
{
    __shared__ float wq[LQv], wa[LAv];
    __shared__ float rd[256], rx[256], ry[256];

    const int b = blockIdx.x;
    const int f0 = blockIdx.y * 200;
    const int tid = threadIdx.x;

    for (int q = tid; q < LQv; q += 256) wq[q] = __uint_as_float(g_mq[b * LQv + q]);
    for (int a = tid; a < LAv; a += 256) wa[a] = __uint_as_float(g_ma[b * LAv + a]);
    __syncthreads();

    float d = 0.0f, x = 0.0f, y = 0.0f;
    if (tid < 200) {
        int f = f0 + tid;
        const float* qp = g_Q + (size_t)b * LQv * FILT + f;
        float accq = 0.0f;
#pragma unroll 8
        for (int q = 0; q < LQv; q++) accq += qp[(size_t)q * FILT] * wq[q];
        const float* ap = g_A + (size_t)b * LAv * FILT + f;
        float acca = 0.0f;
#pragma unroll 8
        for (int a = 0; a < LAv; a++) acca += ap[(size_t)a * FILT] * wa[a];
        d = accq * acca; x = accq * accq; y = acca * acca;
    }
    rd[tid] = d; rx[tid] = x; ry[tid] = y;
    __syncthreads();
#pragma unroll
    for (int s = 128; s > 0; s >>= 1) {
        if (tid < s) {
            rd[tid] += rd[tid + s];
            rx[tid] += rx[tid + s];
            ry[tid] += ry[tid + s];
        }
        __syncthreads();
    }
    if (tid == 0) {
        atomicAdd(&g_dxy[b * 4 + 0], rd[0]);
        atomicAdd(&g_dxy[b * 4 + 1], rx[0]);
        atomicAdd(&g_dxy[b * 4 + 2], ry[0]);
    }
}

// ---------------------------------------------------------------------------
// 4c) final cosine
// ---------------------------------------------------------------------------
__global__ __launch_bounds__(128) void final_out_kernel(float* __restrict__ out)
{
    int b = threadIdx.x;
    float D = g_dxy[b * 4 + 0];
    float X = g_dxy[b * 4 + 1];
    float Y = g_dxy[b * 4 + 2];
    float nq = fmaxf(sqrtf(X), 1e-8f);
    float na = fmaxf(sqrtf(Y), 1e-8f);
    out[b] = D / (nq * na);
}

// ---------------------------------------------------------------------------
// launch — two streams: convA on s2 overlaps convQ + gemm_T on main
// ---------------------------------------------------------------------------
extern "C" void kernel_launch(void* const* d_in, const int* in_sizes, int n_in,
                              void* d_out, int out_size)
{
    const int*   questions = (const int*)d_in[0];
    const int*   answers   = (const int*)d_in[1];
    const float* emb       = (const float*)d_in[2];
    const float* conv_w    = (const float*)d_in[3];
    const float* conv_b    = (const float*)d_in[4];
    const float* W         = (const float*)d_in[5];
    float*       out       = (float*)d_out;

    (void)in_sizes; (void)n_in; (void)out_size;

    static bool init_done = false;
    static cudaStream_t s2;
    static cudaEvent_t evFork, evJoin;
    if (!init_done) {
        cudaFuncSetAttribute(conv_encode_kernel,
                             cudaFuncAttributeMaxDynamicSharedMemorySize, SMEM_CONV);
        cudaFuncSetAttribute(gemm_T_kernel,
                             cudaFuncAttributeMaxDynamicSharedMemorySize, SMEM_T);
        cudaFuncSetAttribute(gemm_G_kernel,
                             cudaFuncAttributeMaxDynamicSharedMemorySize, SMEM_G);
        cudaStreamCreateWithFlags(&s2, cudaStreamNonBlocking);
        cudaEventCreateWithFlags(&evFork, cudaEventDisableTiming);
        cudaEventCreateWithFlags(&evJoin, cudaEventDisableTiming);
        init_done = true;
    }

    init_max_kernel<<<(BATCH * LAv + 255) / 256, 256>>>();
    transpose_w_kernel<<<(5 * KP_TOT * 80 + 255) / 256, 256>>>(conv_w);
    emb_cvt_kernel<<<(int)(((size_t)VROWS * 160 + 255) / 256), 256>>>(emb);

    // fork: convA on s2 after prologue
    cudaEventRecord(evFork, 0);
    cudaStreamWaitEvent(s2, evFork, 0);

    conv_encode_kernel<<<dim3(4, 5, BATCH), 128, SMEM_CONV, s2>>>(
        questions, answers, conv_b, 0);   // answers

    // main stream: convQ then T (Q-only dependency)
    conv_encode_kernel<<<dim3(1, 5, BATCH), 128, SMEM_CONV>>>(
        questions, answers, conv_b, 1);   // questions
    gemm_T_kernel<<<dim3(FILT / 80, 1, BATCH), 128, SMEM_T>>>(W);

    // join: G needs A (s2) and T (main)
    cudaEventRecord(evJoin, s2);
    cudaStreamWaitEvent(0, evJoin, 0);

    gemm_G_kernel<<<dim3(LAv / 128, BATCH), 256, SMEM_G>>>();

    softmax_kernel<<<BATCH, 256>>>();
    pool_kernel<<<dim3(BATCH, 2), 256>>>();
    final_out_kernel<<<1, 128>>>(out);
}

// round 17
// speedup vs baseline: 1.5419x; 1.1681x over previous
#include <cuda_runtime.h>
#include <cuda_bf16.h>
#include <math.h>

#define BATCH 128
#define LQv   128
#define LAv   512
#define EMBD  300
#define FILT  400
#define VROWS 50001
#define KP_TOT 480            // 3 koff * 160 kp
#define FPW   200             // FILT/2 words per packed row

// ---- scratch (static __device__: no allocations allowed) ----
__device__ float    g_Q[BATCH * LQv * FILT];
__device__ unsigned g_Abf[(size_t)BATCH * LAv * FPW];  // bf16-pair A (G + pool)
__device__ unsigned g_Tbf[(size_t)BATCH * LQv * FPW];  // bf16-pair T for G
__device__ unsigned g_Bw[5 * KP_TOT * 80];             // bf16-pair conv weights
__device__ unsigned g_Ebf[(size_t)VROWS * 160];        // bf16-pair padded emb
__device__ unsigned g_mq[BATCH * LQv];
__device__ unsigned g_ma[BATCH * LAv];

__device__ __forceinline__ unsigned enc_f(float f) {
    int i = __float_as_int(f);
    return (unsigned)(i ^ ((i >> 31) | 0x80000000));
}
__device__ __forceinline__ float dec_f(unsigned u) {
    int i = (u & 0x80000000u) ? (int)(u ^ 0x80000000u) : ~(int)u;
    return __int_as_float(i);
}
__device__ __forceinline__ unsigned pack_bf2(float lo, float hi) {
    unsigned short l = __bfloat16_as_ushort(__float2bfloat16(lo));
    unsigned short h = __bfloat16_as_ushort(__float2bfloat16(hi));
    return (unsigned)l | ((unsigned)h << 16);
}
__device__ __forceinline__ void mma8(float* c, const unsigned* a, const unsigned* b) {
    asm("mma.sync.aligned.m16n8k8.row.col.f32.tf32.tf32.f32 "
        "{%0,%1,%2,%3},{%4,%5,%6,%7},{%8,%9},{%0,%1,%2,%3};"
        : "+f"(c[0]), "+f"(c[1]), "+f"(c[2]), "+f"(c[3])
        : "r"(a[0]), "r"(a[1]), "r"(a[2]), "r"(a[3]), "r"(b[0]), "r"(b[1]));
}
__device__ __forceinline__ void mma16(float* c, const unsigned* a, const unsigned* b) {
    asm("mma.sync.aligned.m16n8k16.row.col.f32.bf16.bf16.f32 "
        "{%0,%1,%2,%3},{%4,%5,%6,%7},{%8,%9},{%0,%1,%2,%3};"
        : "+f"(c[0]), "+f"(c[1]), "+f"(c[2]), "+f"(c[3])
        : "r"(a[0]), "r"(a[1]), "r"(a[2]), "r"(a[3]), "r"(b[0]), "r"(b[1]));
}
__device__ __forceinline__ void cp16g(void* sptr, const void* gptr) {
    unsigned s = (unsigned)__cvta_generic_to_shared(sptr);
    asm volatile("cp.async.cg.shared.global [%0], [%1], 16;"
                 :: "r"(s), "l"(gptr));
}
#define CP_COMMIT() asm volatile("cp.async.commit_group;")
#define CP_WAIT0()  asm volatile("cp.async.wait_group 0;")
#define CP_WAIT1()  asm volatile("cp.async.wait_group 1;")

// ---- mbarrier + bulk helpers ----
__device__ __forceinline__ void mbar_init(unsigned addr, unsigned count) {
    asm volatile("mbarrier.init.shared.b64 [%0], %1;" :: "r"(addr), "r"(count) : "memory");
}
__device__ __forceinline__ void mbar_expect_tx(unsigned addr, unsigned bytes) {
    asm volatile("mbarrier.arrive.expect_tx.shared.b64 _, [%0], %1;"
                 :: "r"(addr), "r"(bytes) : "memory");
}
__device__ __forceinline__ void mbar_wait(unsigned addr, unsigned phase) {
    unsigned done = 0;
    while (!done) {
        asm volatile(
            "{\n\t.reg .pred p;\n\t"
            "mbarrier.try_wait.parity.shared.b64 p, [%1], %2;\n\t"
            "selp.b32 %0, 1, 0, p;\n\t}"
            : "=r"(done) : "r"(addr), "r"(phase) : "memory");
    }
}
__device__ __forceinline__ void cp_bulk(void* sptr, const void* gptr,
                                        unsigned bytes, unsigned mbar) {
    unsigned s = (unsigned)__cvta_generic_to_shared(sptr);
    asm volatile(
        "cp.async.bulk.shared::cta.global.mbarrier::complete_tx::bytes "
        "[%0], [%1], %2, [%3];"
        :: "r"(s), "l"(gptr), "r"(bytes), "r"(mbar) : "memory");
}
__device__ __forceinline__ unsigned smem_u32(const void* p) {
    unsigned r;
    asm("{ .reg .u64 t; cvta.to.shared.u64 t, %1; cvt.u32.u64 %0, t; }"
        : "=r"(r) : "l"(p));
    return r;
}

// ---------------------------------------------------------------------------
// 0) init + weight pack + emb convert
// ---------------------------------------------------------------------------
__global__ void init_max_kernel() {
    int idx = blockIdx.x * blockDim.x + threadIdx.x;
    unsigned v = enc_f(-2.0f);
    if (idx < BATCH * LQv) g_mq[idx] = v;
    if (idx < BATCH * LAv) g_ma[idx] = v;
}

__global__ void transpose_w_kernel(const float* __restrict__ cw) {
    int idx = blockIdx.x * blockDim.x + threadIdx.x;
    if (idx >= 5 * KP_TOT * 80) return;
    int nt = idx / (KP_TOT * 80);
    int r  = idx - nt * (KP_TOT * 80);
    int kp = r / 80, nn = r - kp * 80;
    int n = nt * 80 + nn;
    int ko = kp / 160, ep = kp - ko * 160;
    int e0 = 2 * ep, e1 = 2 * ep + 1;
    float v0 = (e0 < EMBD) ? cw[(size_t)n * (EMBD * 3) + e0 * 3 + ko] : 0.0f;
    float v1 = (e1 < EMBD) ? cw[(size_t)n * (EMBD * 3) + e1 * 3 + ko] : 0.0f;
    g_Bw[idx] = pack_bf2(v0, v1);
}

// vectorized: each thread converts 4 floats -> uint2 (2 packed words)
__global__ void emb_cvt_kernel(const float* __restrict__ emb) {
    size_t idx = (size_t)blockIdx.x * blockDim.x + threadIdx.x;
    if (idx >= (size_t)VROWS * 80) return;
    int row = (int)(idx / 80), w4 = (int)(idx - (size_t)row * 80);
    uint2 o = make_uint2(0u, 0u);
    if (w4 < 75) {   // 75 float4 = 300 floats exactly
        float4 v = *(const float4*)&emb[(size_t)row * EMBD + w4 * 4];
        o.x = pack_bf2(v.x, v.y);
        o.y = pack_bf2(v.z, v.w);
    }
    *(uint2*)&g_Ebf[(size_t)row * 160 + w4 * 2] = o;
}

// ---------------------------------------------------------------------------
// 1) conv encode (bf16 m16n8k16), 128 thr, warp 64x40, block 128 tok x 80 f.
//    Epilogue: Q -> f32 g_Q (for T); A -> bf16-packed g_Abf only.
// ---------------------------------------------------------------------------
#define C_NCH  10
#define C_STEPS 30
#define E_PITCH 20
#define E_BUF  (130 * E_PITCH)
#define B_PITCH 80
#define B_STG  (16 * B_PITCH)
#define B_BYTES (B_STG * 4)
#define SM_MBAR 136
#define SM_E_OFF 144
#define SM_B_OFF (SM_E_OFF + 2 * E_BUF)
#define SMEM_CONV ((SM_B_OFF + 2 * B_STG) * 4)

__global__ __launch_bounds__(128, 3) void conv_encode_kernel(
    const int* __restrict__ qtok, const int* __restrict__ atok,
    const float* __restrict__ cb, int is_q)
{
    extern __shared__ unsigned sm[];
    int*      s_tok = (int*)sm;
    unsigned* E     = sm + SM_E_OFF;
    unsigned* Bsm   = sm + SM_B_OFF;

    const int b   = blockIdx.z;
    const int nt  = blockIdx.y;
    const int n0  = nt * 80;
    const int tid = threadIdx.x;
    const int wid = tid >> 5, lane = tid & 31;
    const int g   = lane >> 2, tig = lane & 3;
    const int wm  = wid & 1,  wn  = wid >> 1;
    const int mwb = wm * 64,  nwb = wn * 40;

    const unsigned smem_base = smem_u32(sm);
    const unsigned mbarB0 = smem_base + SM_MBAR * 4;
    const unsigned mbarB1 = smem_base + (SM_MBAR + 2) * 4;

    const int* tok = is_q ? qtok : atok;
    const int L    = is_q ? LQv : LAv;
    const int t0   = blockIdx.x * 128;

    if (tid == 0) { mbar_init(mbarB0, 1); mbar_init(mbarB1, 1); }
    for (int r = tid; r < 130; r += 128) {
        int tg = t0 + r - 1;
        s_tok[r] = (tg >= 0 && tg < L) ? tok[b * L + tg] : 0;
    }
    __syncthreads();

    auto prefetch_E = [&](int ec) {
        unsigned* Eb = E + (ec & 1) * E_BUF;
        int w0 = ec * 16;
        for (int i = tid; i < 130 * 4; i += 128) {
            int r = i >> 2, sg = i & 3;
            cp16g(&Eb[r * E_PITCH + sg * 4],
                  g_Ebf + (size_t)s_tok[r] * 160 + w0 + sg * 4);
        }
        CP_COMMIT();
    };
    auto prefetch_B = [&](int s) {
        if (tid == 0) {
            int ec = s / 3, ko = s - ec * 3;
            unsigned mb = (s & 1) ? mbarB1 : mbarB0;
            mbar_expect_tx(mb, B_BYTES);
            const unsigned* src =
                g_Bw + ((size_t)nt * KP_TOT + ko * 160 + ec * 16) * 80;
            cp_bulk(Bsm + (s & 1) * B_STG, src, B_BYTES, mb);
        }
    };

    float c[4][5][4];
#pragma unroll
    for (int i = 0; i < 4; i++)
#pragma unroll
        for (int j = 0; j < 5; j++)
#pragma unroll
            for (int k = 0; k < 4; k++) c[i][j][k] = 0.0f;

    prefetch_E(0);
    prefetch_B(0);

    for (int s = 0; s < C_STEPS; s++) {
        const int ec = s / 3, ko = s - ec * 3;
        const int ebs = ec & 1, bbs = s & 1;

        mbar_wait(bbs ? mbarB1 : mbarB0, (s >> 1) & 1);
        if (ko == 0) CP_WAIT0();
        __syncthreads();

        if (ko == 0 && ec + 1 < C_NCH) prefetch_E(ec + 1);
        if (s + 1 < C_STEPS) prefetch_B(s + 1);

        const unsigned* Eb = E + ebs * E_BUF;
        const unsigned* Bk = Bsm + bbs * B_STG;

#pragma unroll
        for (int kb = 0; kb < 2; kb++) {
            int kk = kb * 8;
            unsigned a[4][4];
#pragma unroll
            for (int ms = 0; ms < 4; ms++) {
                int row = mwb + ms * 16 + g + ko;
                a[ms][0] = Eb[(row)     * E_PITCH + kk + tig];
                a[ms][1] = Eb[(row + 8) * E_PITCH + kk + tig];
                a[ms][2] = Eb[(row)     * E_PITCH + kk + tig + 4];
                a[ms][3] = Eb[(row + 8) * E_PITCH + kk + tig + 4];
            }
#pragma unroll
            for (int ns = 0; ns < 5; ns++) {
                unsigned bf[2];
                int nb = nwb + ns * 8 + g;
                bf[0] = Bk[(kk + tig)     * B_PITCH + nb];
                bf[1] = Bk[(kk + tig + 4) * B_PITCH + nb];
#pragma unroll
                for (int ms = 0; ms < 4; ms++)
                    mma16(c[ms][ns], a[ms], bf);
            }
        }
    }

#pragma unroll
    for (int ms = 0; ms < 4; ms++) {
#pragma unroll
        for (int ns = 0; ns < 5; ns++) {
            int col = n0 + nwb + ns * 8 + 2 * tig;
            float2 bias = *(const float2*)&cb[col];
            int row0 = t0 + mwb + ms * 16 + g;
            float v0 = c[ms][ns][0] + bias.x, v1 = c[ms][ns][1] + bias.y;
            float v2 = c[ms][ns][2] + bias.x, v3 = c[ms][ns][3] + bias.y;
            if (is_q) {
                *(float2*)&g_Q[((size_t)b * LQv + row0) * FILT + col] = make_float2(v0, v1);
                *(float2*)&g_Q[((size_t)b * LQv + row0 + 8) * FILT + col] = make_float2(v2, v3);
            } else {
                g_Abf[((size_t)b * LAv + row0) * FPW + (col >> 1)] = pack_bf2(v0, v1);
                g_Abf[((size_t)b * LAv + row0 + 8) * FPW + (col >> 1)] = pack_bf2(v2, v3);
            }
        }
    }
}

// ---------------------------------------------------------------------------
// 2) T = Qm @ W : tf32 compute (hidden under convA), bf16-packed output
// ---------------------------------------------------------------------------
#define T_KC 40
#define T_AP 44
#define T_BP 88
#define T_ABUF (128 * T_AP)
#define T_BOFF (2 * T_ABUF)
#define T_BBUF (T_KC * T_BP)
#define SMEM_T ((T_BOFF + 2 * T_BBUF) * 4)

__global__ __launch_bounds__(128, 2) void gemm_T_kernel(const float* __restrict__ W)
{
    extern __shared__ unsigned sm[];
    unsigned* Asm = sm;
    unsigned* Bsm = sm + T_BOFF;

    const int b  = blockIdx.z;
    const int n0 = blockIdx.x * 80;
    const int tid  = threadIdx.x;
    const int wid  = tid >> 5, lane = tid & 31;
    const int g    = lane >> 2, tig = lane & 3;
    const int wm   = wid & 1,  wn  = wid >> 1;
    const int mwb  = wm * 64, nwb = wn * 40;

    const float* Qb = g_Q + (size_t)b * LQv * FILT;

    auto prefetch = [&](int ch, int bs) {
        int k0 = ch * T_KC;
        unsigned* Ab = Asm + bs * T_ABUF;
        unsigned* Bb = Bsm + bs * T_BBUF;
#pragma unroll
        for (int it = 0; it < 10; it++) {
            int i = tid + it * 128;
            int m = i / 10, k4 = i - m * 10;
            cp16g(&Ab[m * T_AP + k4 * 4], Qb + (size_t)m * FILT + k0 + k4 * 4);
        }
        for (int i = tid; i < T_KC * 20; i += 128) {
            int kc = i / 20, sg = i - kc * 20;
            cp16g(&Bb[kc * T_BP + sg * 4], W + (size_t)(k0 + kc) * FILT + n0 + sg * 4);
        }
    };

    float c[4][5][4];
#pragma unroll
    for (int i = 0; i < 4; i++)
#pragma unroll
        for (int j = 0; j < 5; j++)
#pragma unroll
            for (int k = 0; k < 4; k++) c[i][j][k] = 0.0f;

    prefetch(0, 0);
    CP_COMMIT();

    for (int ch = 0; ch < FILT / T_KC; ch++) {
        int bs = ch & 1;
        if (ch + 1 < FILT / T_KC) prefetch(ch + 1, bs ^ 1);
        CP_COMMIT();
        CP_WAIT1();
        __syncthreads();

        const unsigned* Ab = Asm + bs * T_ABUF;
        const unsigned* Bb = Bsm + bs * T_BBUF;

#pragma unroll
        for (int kb = 0; kb < T_KC / 8; kb++) {
            int kk = kb * 8;
            unsigned a[4][4];
#pragma unroll
            for (int ms = 0; ms < 4; ms++) {
                int row = mwb + ms * 16 + g;
                a[ms][0] = Ab[(row)     * T_AP + kk + tig];
                a[ms][1] = Ab[(row + 8) * T_AP + kk + tig];
                a[ms][2] = Ab[(row)     * T_AP + kk + tig + 4];
                a[ms][3] = Ab[(row + 8) * T_AP + kk + tig + 4];
            }
#pragma unroll
            for (int ns = 0; ns < 5; ns++) {
                unsigned bf[2];
                int nb = nwb + ns * 8 + g;
                bf[0] = Bb[(kk + tig)     * T_BP + nb];
                bf[1] = Bb[(kk + tig + 4) * T_BP + nb];
#pragma unroll
                for (int ms = 0; ms < 4; ms++)
                    mma8(c[ms][ns], a[ms], bf);
            }
        }
        __syncthreads();
    }

#pragma unroll
    for (int ms = 0; ms < 4; ms++) {
#pragma unroll
        for (int ns = 0; ns < 5; ns++) {
            int col = n0 + nwb + ns * 8 + 2 * tig;
            int row0 = mwb + ms * 16 + g;
            g_Tbf[((size_t)b * LQv + row0) * FPW + (col >> 1)] =
                pack_bf2(c[ms][ns][0], c[ms][ns][1]);
            g_Tbf[((size_t)b * LQv + row0 + 8) * FPW + (col >> 1)] =
                pack_bf2(c[ms][ns][2], c[ms][ns][3]);
        }
    }
}

// ---------------------------------------------------------------------------
// 3) G = tanh(T @ A^T) fused maxes: bf16 m16n8k16, 256 thr, warp 64x32,
//    block 128 x 128, 5 K-chunks of 40 words, bulk + mbarrier pipeline
// ---------------------------------------------------------------------------
#define G_KW 40
#define G_AP 44
#define G_ABUF (128 * G_AP)
#define G_BOFF (2 * G_ABUF)
#define G_BBUF (128 * G_AP)
#define G_RED  (G_BOFF + 2 * G_BBUF)
#define G_MBAR (G_RED + 256)
#define SMEM_G ((G_MBAR + 8) * 4)
#define G_ROW_BYTES (G_KW * 4)

__global__ __launch_bounds__(256, 2) void gemm_G_kernel()
{
    extern __shared__ unsigned sm[];
    unsigned* Asm  = sm;
    unsigned* Bsm  = sm + G_BOFF;
    unsigned* srow = sm + G_RED;
    unsigned* scol = sm + G_RED + 128;

    const int b  = blockIdx.y;
    const int a0 = blockIdx.x * 128;
    const int tid  = threadIdx.x;
    const int wid  = tid >> 5, lane = tid & 31;
    const int g    = lane >> 2, tig = lane & 3;
    const int wm   = wid & 1,  wn  = wid >> 1;
    const int mwb  = wm * 64, nwb = wn * 32;

    const unsigned smem_base = smem_u32(sm);
    const unsigned mbar0 = smem_base + G_MBAR * 4;
    const unsigned mbar1 = smem_base + (G_MBAR + 2) * 4;

    if (tid == 0) { mbar_init(mbar0, 1); mbar_init(mbar1, 1); }
    if (tid < 128) { srow[tid] = enc_f(-2.0f); scol[tid] = enc_f(-2.0f); }
    __syncthreads();

    const unsigned* Tb  = g_Tbf + (size_t)b * LQv * FPW;
    const unsigned* Ab0 = g_Abf + ((size_t)b * LAv + a0) * FPW;

    auto prefetch = [&](int ch, int bs) {
        int k0 = ch * G_KW;
        unsigned mb = bs ? mbar1 : mbar0;
        if (tid == 0) mbar_expect_tx(mb, 256 * G_ROW_BYTES);
        if (tid < 128) {
            cp_bulk(&(Asm + bs * G_ABUF)[tid * G_AP],
                    Tb + (size_t)tid * FPW + k0, G_ROW_BYTES, mb);
        } else {
            int n = tid - 128;
            cp_bulk(&(Bsm + bs * G_BBUF)[n * G_AP],
                    Ab0 + (size_t)n * FPW + k0, G_ROW_BYTES, mb);
        }
    };

    float c[4][4][4];
#pragma unroll
    for (int i = 0; i < 4; i++)
#pragma unroll
        for (int j = 0; j < 4; j++)
#pragma unroll
            for (int k = 0; k < 4; k++) c[i][j][k] = 0.0f;

    prefetch(0, 0);

    for (int ch = 0; ch < 5; ch++) {
        int bs = ch & 1;
        if (ch + 1 < 5) prefetch(ch + 1, bs ^ 1);
        mbar_wait(bs ? mbar1 : mbar0, (ch >> 1) & 1);
        __syncthreads();

        const unsigned* Abuf = Asm + bs * G_ABUF;
        const unsigned* Bbuf = Bsm + bs * G_BBUF;

#pragma unroll
        for (int kb = 0; kb < 5; kb++) {
            int kk = kb * 8;
            unsigned a[4][4];
#pragma unroll
            for (int ms = 0; ms < 4; ms++) {
                int row = mwb + ms * 16 + g;
                a[ms][0] = Abuf[(row)     * G_AP + kk + tig];
                a[ms][1] = Abuf[(row + 8) * G_AP + kk + tig];
                a[ms][2] = Abuf[(row)     * G_AP + kk + tig + 4];
                a[ms][3] = Abuf[(row + 8) * G_AP + kk + tig + 4];
            }
#pragma unroll
            for (int ns = 0; ns < 4; ns++) {
                unsigned bf[2];
                int nb = nwb + ns * 8 + g;
                bf[0] = Bbuf[nb * G_AP + kk + tig];
                bf[1] = Bbuf[nb * G_AP + kk + tig + 4];
#pragma unroll
                for (int ms = 0; ms < 4; ms++)
                    mma16(c[ms][ns], a[ms], bf);
            }
        }
        __syncthreads();
    }

#pragma unroll
    for (int ms = 0; ms < 4; ms++) {
        float r0 = -2.0f, r1 = -2.0f;
#pragma unroll
        for (int ns = 0; ns < 4; ns++) {
#pragma unroll
            for (int k = 0; k < 4; k++) c[ms][ns][k] = tanhf(c[ms][ns][k]);
            r0 = fmaxf(r0, fmaxf(c[ms][ns][0], c[ms][ns][1]));
            r1 = fmaxf(r1, fmaxf(c[ms][ns][2], c[ms][ns][3]));
        }
        atomicMax(&srow[mwb + ms * 16 + g],     enc_f(r0));
        atomicMax(&srow[mwb + ms * 16 + g + 8], enc_f(r1));
    }
#pragma unroll
    for (int ns = 0; ns < 4; ns++) {
        float c0 = -2.0f, c1 = -2.0f;
#pragma unroll
        for (int ms = 0; ms < 4; ms++) {
            c0 = fmaxf(c0, fmaxf(c[ms][ns][0], c[ms][ns][2]));
            c1 = fmaxf(c1, fmaxf(c[ms][ns][1], c[ms][ns][3]));
        }
        int nb = nwb + ns * 8 + 2 * tig;
        atomicMax(&scol[nb],     enc_f(c0));
        atomicMax(&scol[nb + 1], enc_f(c1));
    }
    __syncthreads();

    if (tid < 128) {
        atomicMax(&g_mq[b * LQv + tid], srow[tid]);
        atomicMax(&g_ma[b * LAv + a0 + tid], scol[tid]);
    }
}

// ---------------------------------------------------------------------------
// 4a) per-batch softmax; writes normalized weights back into g_mq / g_ma
// ---------------------------------------------------------------------------
__device__ __forceinline__ float warp_max(float v) {
#pragma unroll
    for (int o = 16; o > 0; o >>= 1) v = fmaxf(v, __shfl_xor_sync(0xffffffffu, v, o));
    return v;
}
__device__ __forceinline__ float warp_sum(float v) {
#pragma unroll
    for (int o = 16; o > 0; o >>= 1) v += __shfl_xor_sync(0xffffffffu, v, o);
    return v;
}

__global__ __launch_bounds__(256) void softmax_kernel()
{
    __shared__ float sq[LQv], sa[LAv];
    __shared__ float smax[2], ssum[2];

    const int b = blockIdx.x;
    const int tid = threadIdx.x;
    const int lane = tid & 31;

    for (int q = tid; q < LQv; q += 256) sq[q] = dec_f(g_mq[b * LQv + q]);
    for (int a = tid; a < LAv; a += 256) sa[a] = dec_f(g_ma[b * LAv + a]);
    __syncthreads();

    if (tid < 32) {
        float m = -1e30f;
        for (int q = lane; q < LQv; q += 32) m = fmaxf(m, sq[q]);
        m = warp_max(m);
        if (lane == 0) smax[0] = m;
    } else if (tid < 64) {
        float m = -1e30f;
        for (int a = lane; a < LAv; a += 32) m = fmaxf(m, sa[a]);
        m = warp_max(m);
        if (lane == 0) smax[1] = m;
    }
    __syncthreads();
    for (int q = tid; q < LQv; q += 256) sq[q] = expf(sq[q] - smax[0]);
    for (int a = tid; a < LAv; a += 256) sa[a] = expf(sa[a] - smax[1]);
    __syncthreads();
    if (tid < 32) {
        float s = 0.0f;
        for (int q = lane; q < LQv; q += 32) s += sq[q];
        s = warp_sum(s);
        if (lane == 0) ssum[0] = s;
    } else if (tid < 64) {
        float s = 0.0f;
        for (int a = lane; a < LAv; a += 32) s += sa[a];
        s = warp_sum(s);
        if (lane == 0) ssum[1] = s;
    }
    __syncthreads();
    float invq = 1.0f / ssum[0], inva = 1.0f / ssum[1];
    for (int q = tid; q < LQv; q += 256)
        g_mq[b * LQv + q] = __float_as_uint(sq[q] * invq);
    for (int a = tid; a < LAv; a += 256)
        g_ma[b * LAv + a] = __float_as_uint(sa[a] * inva);
}

// ---------------------------------------------------------------------------
// 4b) pool + cosine: one block per batch; 200 threads, 2 filters each.
//     Q from f32 g_Q; A from bf16-packed g_Abf.
// ---------------------------------------------------------------------------
__global__ __launch_bounds__(256) void pool_kernel(float* __restrict__ out)
{
    __shared__ float wq[LQv], wa[LAv];
    __shared__ float rd[256], rx[256], ry[256];

    const int b = blockIdx.x;
    const int tid = threadIdx.x;

    for (int q = tid; q < LQv; q += 256) wq[q] = __uint_as_float(g_mq[b * LQv + q]);
    for (int a = tid; a < LAv; a += 256) wa[a] = __uint_as_float(g_ma[b * LAv + a]);
    __syncthreads();

    float d = 0.0f, x = 0.0f, y = 0.0f;
    if (tid < FPW) {
        const float* qp = g_Q + (size_t)b * LQv * FILT + 2 * tid;
        float aq0 = 0.0f, aq1 = 0.0f;
#pragma unroll 8
        for (int q = 0; q < LQv; q++) {
            float2 v = *(const float2*)&qp[(size_t)q * FILT];
            aq0 += v.x * wq[q];
            aq1 += v.y * wq[q];
        }
        const unsigned* ap = g_Abf + (size_t)b * LAv * FPW + tid;
        float aa0 = 0.0f, aa1 = 0.0f;
#pragma unroll 8
        for (int a = 0; a < LAv; a++) {
            unsigned u = ap[(size_t)a * FPW];
            aa0 += __uint_as_float(u << 16) * wa[a];
            aa1 += __uint_as_float(u & 0xffff0000u) * wa[a];
        }
        d = aq0 * aa0 + aq1 * aa1;
        x = aq0 * aq0 + aq1 * aq1;
        y = aa0 * aa0 + aa1 * aa1;
    }
    rd[tid] = d; rx[tid] = x; ry[tid] = y;
    __syncthreads();
#pragma unroll
    for (int s = 128; s > 0; s >>= 1) {
        if (tid < s) {
            rd[tid] += rd[tid + s];
            rx[tid] += rx[tid + s];
            ry[tid] += ry[tid + s];
        }
        __syncthreads();
    }
    if (tid == 0) {
        float nq = fmaxf(sqrtf(rx[0]), 1e-8f);
        float na = fmaxf(sqrtf(ry[0]), 1e-8f);
        out[b] = rd[0] / (nq * na);
    }
}

// ---------------------------------------------------------------------------
// launch — all prologue on main stream, then legal fork: s2 waits on evFork
// ---------------------------------------------------------------------------
extern "C" void kernel_launch(void* const* d_in, const int* in_sizes, int n_in,
                              void* d_out, int out_size)
{
    const int*   questions = (const int*)d_in[0];
    const int*   answers   = (const int*)d_in[1];
    const float* emb       = (const float*)d_in[2];
    const float* conv_w    = (const float*)d_in[3];
    const float* conv_b    = (const float*)d_in[4];
    const float* W         = (const float*)d_in[5];
    float*       out       = (float*)d_out;

    (void)in_sizes; (void)n_in; (void)out_size;

    static bool init_done = false;
    static cudaStream_t s2;
    static cudaEvent_t evFork, evJoin;
    if (!init_done) {
        cudaFuncSetAttribute(conv_encode_kernel,
                             cudaFuncAttributeMaxDynamicSharedMemorySize, SMEM_CONV);
        cudaFuncSetAttribute(gemm_T_kernel,
                             cudaFuncAttributeMaxDynamicSharedMemorySize, SMEM_T);
        cudaFuncSetAttribute(gemm_G_kernel,
                             cudaFuncAttributeMaxDynamicSharedMemorySize, SMEM_G);
        cudaStreamCreateWithFlags(&s2, cudaStreamNonBlocking);
        cudaEventCreateWithFlags(&evFork, cudaEventDisableTiming);
        cudaEventCreateWithFlags(&evJoin, cudaEventDisableTiming);
        init_done = true;
    }

    // prologue entirely on the capture-origin stream
    init_max_kernel<<<(BATCH * LAv + 255) / 256, 256>>>();
    transpose_w_kernel<<<(5 * KP_TOT * 80 + 255) / 256, 256>>>(conv_w);
    emb_cvt_kernel<<<(int)(((size_t)VROWS * 80 + 255) / 256), 256>>>(emb);

    // fork: convA on s2 after prologue
    cudaEventRecord(evFork, 0);
    cudaStreamWaitEvent(s2, evFork, 0);
    conv_encode_kernel<<<dim3(4, 5, BATCH), 128, SMEM_CONV, s2>>>(
        questions, answers, conv_b, 0);   // answers

    // main: convQ then T (Q-only dependency)
    conv_encode_kernel<<<dim3(1, 5, BATCH), 128, SMEM_CONV>>>(
        questions, answers, conv_b, 1);   // questions
    gemm_T_kernel<<<dim3(FILT / 80, 1, BATCH), 128, SMEM_T>>>(W);

    // join: G needs A (s2) and T (main)
    cudaEventRecord(evJoin, s2);
    cudaStreamWaitEvent(0, evJoin, 0);

    gemm_G_kernel<<<dim3(LAv / 128, BATCH), 256, SMEM_G>>>();

    softmax_kernel<<<BATCH, 256>>>();
    pool_kernel<<<BATCH, 256>>>(out);
}